// round 6
// baseline (speedup 1.0000x reference)
#include <cuda_runtime.h>
#include <cuda_bf16.h>
#include <cstdint>

#define NB  4
#define NS  2048
#define ND  512
#define NH  8
#define NDH 64

// ---------------------------------------------------------------------------
// Scratch (device globals: allocation-free rule)
// ---------------------------------------------------------------------------
__device__ __nv_bfloat16 g_qh[NB * NH * NS * NDH];
__device__ __nv_bfloat16 g_ql[NB * NH * NS * NDH];
__device__ __nv_bfloat16 g_kh[NB * NH * NS * NDH];
__device__ __nv_bfloat16 g_kl[NB * NH * NS * NDH];
__device__ __nv_bfloat16 g_vh[NB * NH * NS * NDH];
__device__ __nv_bfloat16 g_vl[NB * NH * NS * NDH];
__device__ __nv_bfloat16 g_ch[NB * NS * ND];
__device__ __nv_bfloat16 g_cl[NB * NS * ND];
__device__ __nv_bfloat16 g_ah[3][NB * NS * ND];
__device__ __nv_bfloat16 g_al[3][NB * NS * ND];
__device__ __nv_bfloat16 g_wh[4][ND * ND];
__device__ __nv_bfloat16 g_wl[4][ND * ND];

// ---------------------------------------------------------------------------
__device__ __forceinline__ uint32_t smem_u32(const void* p) {
    uint32_t a;
    asm("{ .reg .u64 t; cvta.to.shared.u64 t, %1; cvt.u32.u64 %0, t; }"
        : "=r"(a) : "l"(p));
    return a;
}
__device__ __forceinline__ void cp_async16(uint32_t dst, const void* src) {
    asm volatile("cp.async.ca.shared.global [%0], [%1], 16;"
                 :: "r"(dst), "l"(src) : "memory");
}
__device__ __forceinline__ void cp_commit() {
    asm volatile("cp.async.commit_group;" ::: "memory");
}
__device__ __forceinline__ void ldsm_x4(uint32_t addr, uint32_t& r0, uint32_t& r1,
                                        uint32_t& r2, uint32_t& r3) {
    asm volatile("ldmatrix.sync.aligned.m8n8.x4.shared.b16 {%0,%1,%2,%3}, [%4];"
                 : "=r"(r0), "=r"(r1), "=r"(r2), "=r"(r3) : "r"(addr));
}
__device__ __forceinline__ void ldsm_x4_t(uint32_t addr, uint32_t& r0, uint32_t& r1,
                                          uint32_t& r2, uint32_t& r3) {
    asm volatile("ldmatrix.sync.aligned.m8n8.x4.trans.shared.b16 {%0,%1,%2,%3}, [%4];"
                 : "=r"(r0), "=r"(r1), "=r"(r2), "=r"(r3) : "r"(addr));
}
__device__ __forceinline__ void mma16816(float* c, const uint32_t* a, const uint32_t* b) {
    asm volatile(
        "mma.sync.aligned.m16n8k16.row.col.f32.bf16.bf16.f32 "
        "{%0,%1,%2,%3}, {%4,%5,%6,%7}, {%8,%9}, {%0,%1,%2,%3};"
        : "+f"(c[0]), "+f"(c[1]), "+f"(c[2]), "+f"(c[3])
        : "r"(a[0]), "r"(a[1]), "r"(a[2]), "r"(a[3]), "r"(b[0]), "r"(b[1]));
}
__device__ __forceinline__ float ex2(float x) {
    float y;
    asm("ex2.approx.ftz.f32 %0, %1;" : "=f"(y) : "f"(x));
    return y;
}
__device__ __forceinline__ uint32_t pack_bf2(float a, float b) {
    __nv_bfloat162 t = __floats2bfloat162_rn(a, b);
    return *(uint32_t*)&t;
}

// ---------------------------------------------------------------------------
// Merged fp32 -> bf16 hi/lo split conversion (blockIdx.y selects tensor)
// ---------------------------------------------------------------------------
struct ConvArgs {
    const float* in[4];
    __nv_bfloat16* hi[4];
    __nv_bfloat16* lo[4];
    int n4;
};

__global__ __launch_bounds__(256) void conv_multi(ConvArgs a)
{
    const int which = blockIdx.y;
    const float* in = a.in[which];
    __nv_bfloat16* hi = a.hi[which];
    __nv_bfloat16* lo = a.lo[which];
    int idx = blockIdx.x * 256 + threadIdx.x;
    if (idx >= a.n4) return;
    float4 v = ((const float4*)in)[idx];
    float f[4] = {v.x, v.y, v.z, v.w};
    __nv_bfloat16 h[4], l[4];
#pragma unroll
    for (int i = 0; i < 4; ++i) {
        h[i] = __float2bfloat16_rn(f[i]);
        l[i] = __float2bfloat16_rn(f[i] - __bfloat162float(h[i]));
    }
    ((uint2*)hi)[idx] = *(uint2*)h;
    ((uint2*)lo)[idx] = *(uint2*)l;
}

// ---------------------------------------------------------------------------
// HMMA projection GEMM (R4-proven inner loop): C = X @ W^T + bias
// MODE 0: fp32 row-major out. MODE 1: fused QKV via blockIdx.z, bf16 hi/lo out.
// ---------------------------------------------------------------------------
#define ROWB   80
#define ARRSZ  10240
#define STAGESZ (4 * ARRSZ)
#define PROJ_SMEM (2 * STAGESZ)

struct ProjArgs {
    const __nv_bfloat16* Ah[3];
    const __nv_bfloat16* Al[3];
    const __nv_bfloat16* Bh[3];
    const __nv_bfloat16* Bl[3];
    const float* bias[3];
    __nv_bfloat16* oH[3];
    __nv_bfloat16* oL[3];
    float* oF;
    float scale[3];
};

template <int MODE>
__global__ __launch_bounds__(256) void proj_hmma(ProjArgs pa)
{
    extern __shared__ char smem[];
    const uint32_t sb = smem_u32(smem);
    const int z   = (MODE == 1) ? blockIdx.z : 0;
    const __nv_bfloat16* __restrict__ Ah = pa.Ah[z];
    const __nv_bfloat16* __restrict__ Al = pa.Al[z];
    const __nv_bfloat16* __restrict__ Bh = pa.Bh[z];
    const __nv_bfloat16* __restrict__ Bl = pa.Bl[z];
    const float* __restrict__ bias = pa.bias[z];

    const int tid  = threadIdx.x;
    const int lane = tid & 31;
    const int wid  = tid >> 5;
    const int warp_m = wid & 3;
    const int warp_n = wid >> 2;
    const int m0 = blockIdx.x * 128;
    const int n0 = blockIdx.y * 128;

    const int r0c = (tid + 0)   >> 2, s0c = tid & 3;
    const int r1c = (tid + 256) >> 2, s1c = tid & 3;

    const uint32_t a_off = (uint32_t)((warp_m * 32 + (lane & 15)) * ROWB + (lane >> 4) * 16);
    const uint32_t b_off = (uint32_t)((warp_n * 64 + (lane & 7) + 8 * (lane >> 4)) * ROWB
                                      + ((lane >> 3) & 1) * 16);

    float acc[2][8][4];
#pragma unroll
    for (int mi = 0; mi < 2; ++mi)
#pragma unroll
        for (int ni = 0; ni < 8; ++ni)
#pragma unroll
            for (int q = 0; q < 4; ++q) acc[mi][ni][q] = 0.0f;

    auto load_chunk = [&](int c, int stage) {
        const int k0 = c * 32;
        const uint32_t st = sb + stage * STAGESZ;
        const __nv_bfloat16* srcs[4] = {Ah, Al, Bh, Bl};
#pragma unroll
        for (int arr = 0; arr < 4; ++arr) {
            const __nv_bfloat16* base = srcs[arr];
            const int rbase = (arr < 2) ? m0 : n0;
            cp_async16(st + arr * ARRSZ + r0c * ROWB + s0c * 16,
                       base + (rbase + r0c) * ND + k0 + s0c * 8);
            cp_async16(st + arr * ARRSZ + r1c * ROWB + s1c * 16,
                       base + (rbase + r1c) * ND + k0 + s1c * 8);
        }
        cp_commit();
    };

    load_chunk(0, 0);

    for (int c = 0; c < 16; ++c) {
        const int stage = c & 1;
        if (c < 15) {
            load_chunk(c + 1, stage ^ 1);
            asm volatile("cp.async.wait_group 1;" ::: "memory");
        } else {
            asm volatile("cp.async.wait_group 0;" ::: "memory");
        }
        __syncthreads();

        const uint32_t st = sb + stage * STAGESZ;
#pragma unroll
        for (int ks = 0; ks < 2; ++ks) {
            const uint32_t kb = ks * 32;
            uint32_t ah[2][4], al[2][4];
#pragma unroll
            for (int mi = 0; mi < 2; ++mi) {
                uint32_t adr = st + a_off + mi * (16 * ROWB) + kb;
                ldsm_x4(adr,         ah[mi][0], ah[mi][1], ah[mi][2], ah[mi][3]);
                ldsm_x4(adr + ARRSZ, al[mi][0], al[mi][1], al[mi][2], al[mi][3]);
            }
            uint32_t bh[8][2], bl[8][2];
#pragma unroll
            for (int nb = 0; nb < 4; ++nb) {
                uint32_t adr = st + 2 * ARRSZ + b_off + nb * (16 * ROWB) + kb;
                uint32_t t0, t1, t2, t3;
                ldsm_x4(adr, t0, t1, t2, t3);
                bh[nb*2][0] = t0; bh[nb*2][1] = t1; bh[nb*2+1][0] = t2; bh[nb*2+1][1] = t3;
                ldsm_x4(adr + ARRSZ, t0, t1, t2, t3);
                bl[nb*2][0] = t0; bl[nb*2][1] = t1; bl[nb*2+1][0] = t2; bl[nb*2+1][1] = t3;
            }
#pragma unroll
            for (int mi = 0; mi < 2; ++mi)
#pragma unroll
                for (int ni = 0; ni < 8; ++ni) {
                    mma16816(acc[mi][ni], ah[mi], bh[ni]);
                    mma16816(acc[mi][ni], ah[mi], bl[ni]);
                    mma16816(acc[mi][ni], al[mi], bh[ni]);
                }
        }
        __syncthreads();
    }

    const float scale = pa.scale[z];
    const int crow = lane >> 2;
    const int ccol = (lane & 3) * 2;
#pragma unroll
    for (int mi = 0; mi < 2; ++mi) {
#pragma unroll
        for (int half = 0; half < 2; ++half) {
            const int m = m0 + warp_m * 32 + mi * 16 + crow + half * 8;
            const int b = m >> 11, s = m & 2047;
#pragma unroll
            for (int ni = 0; ni < 8; ++ni) {
                const int n = n0 + warp_n * 64 + ni * 8 + ccol;
                float v0 = acc[mi][ni][half * 2 + 0] + bias[n];
                float v1 = acc[mi][ni][half * 2 + 1] + bias[n + 1];
                if (MODE == 1) {
                    v0 *= scale; v1 *= scale;
                    const int head = n >> 6, d = n & 63;
                    const int idx = ((b * NH + head) * NS + s) * NDH + d;
                    __nv_bfloat16 h0 = __float2bfloat16_rn(v0);
                    __nv_bfloat16 h1 = __float2bfloat16_rn(v1);
                    *(uint32_t*)&pa.oH[z][idx] =
                        pack_bf2(__bfloat162float(h0), __bfloat162float(h1));
                    *(uint32_t*)&pa.oL[z][idx] =
                        pack_bf2(v0 - __bfloat162float(h0), v1 - __bfloat162float(h1));
                } else {
                    *(float2*)&pa.oF[m * ND + n] = make_float2(v0, v1);
                }
            }
        }
    }
}

// ---------------------------------------------------------------------------
// HMMA flash attention. CTA = 256 q rows x one (b,h), 512 threads (16 warps,
// occ 50%). KV tile 64, cp.async double-buffered. q pre-scaled by
// 0.125*log2(e); softmax in log2 domain; S/PV via bf16 hi/lo.
// ---------------------------------------------------------------------------
#define QROWB 144
#define QARR  36864          // 256 rows x 144B
#define KARRA 9216           // 64 rows x 144B
#define KVSTG (4 * KARRA)    // 36864
#define ATTN_SMEM (2 * QARR + 2 * KVSTG)   // 147456

__global__ __launch_bounds__(512) void attn_hmma(
    const __nv_bfloat16* __restrict__ qh, const __nv_bfloat16* __restrict__ ql,
    const __nv_bfloat16* __restrict__ kh, const __nv_bfloat16* __restrict__ kl,
    const __nv_bfloat16* __restrict__ vh, const __nv_bfloat16* __restrict__ vl,
    __nv_bfloat16* __restrict__ ch, __nv_bfloat16* __restrict__ cl,
    const void* __restrict__ masked_raw)
{
    extern __shared__ char smem[];
    const uint32_t sb = smem_u32(smem);
    const int tid  = threadIdx.x;
    const int lane = tid & 31;
    const int wid  = tid >> 5;           // 0..15
    const int bh   = blockIdx.y;
    const int b    = bh >> 3;
    const int h    = bh & 7;
    const int q0   = blockIdx.x << 8;    // 256 q rows per CTA
    const int gbase = bh * NS * NDH;

    int len;
    {
        const long long* ml = (const long long*)masked_raw;
        long long probe = ml[0];
        if (probe >= 1 && probe <= NS) len = (int)ml[b];
        else                           len = ((const int*)masked_raw)[b];
    }
    const int ntiles = (len + 63) >> 6;

    // Load Q hi/lo into smem: 256 rows x 8 blks = 2048 lines / 512 thr = 4 it
#pragma unroll
    for (int i = 0; i < 4; ++i) {
        int c = tid + i * 512;
        int r = c >> 3, blk = c & 7;
        const int src = gbase + (q0 + r) * NDH + blk * 8;
        *(uint4*)(smem + r * QROWB + blk * 16)        = *(const uint4*)(qh + src);
        *(uint4*)(smem + QARR + r * QROWB + blk * 16) = *(const uint4*)(ql + src);
    }

    auto load_kv = [&](int t, int stg) {
        const uint32_t s0 = sb + 2 * QARR + stg * KVSTG;
        const int gk = gbase + (t << 6) * NDH;
        // 64 rows x 8 blks = 512 lines, one per thread
        int r = tid >> 3, blk = tid & 7;
        const uint32_t dst = s0 + r * QROWB + blk * 16;
        const int src = gk + r * NDH + blk * 8;
        cp_async16(dst,             kh + src);
        cp_async16(dst + KARRA,     kl + src);
        cp_async16(dst + 2*KARRA,   vh + src);
        cp_async16(dst + 3*KARRA,   vl + src);
        cp_commit();
    };

    load_kv(0, 0);
    __syncthreads();   // Q smem ready

    uint32_t qfh[4][4], qfl[4][4];
    {
        const uint32_t qa = sb + (wid * 16 + (lane & 15)) * QROWB + (lane >> 4) * 16;
#pragma unroll
        for (int ks = 0; ks < 4; ++ks) {
            ldsm_x4(qa + ks * 32,        qfh[ks][0], qfh[ks][1], qfh[ks][2], qfh[ks][3]);
            ldsm_x4(qa + ks * 32 + QARR, qfl[ks][0], qfl[ks][1], qfl[ks][2], qfl[ks][3]);
        }
    }

    float m0r = -1e30f, m1r = -1e30f, lsum0 = 0.0f, lsum1 = 0.0f;
    float o[8][4];
#pragma unroll
    for (int di = 0; di < 8; ++di)
#pragma unroll
        for (int q = 0; q < 4; ++q) o[di][q] = 0.0f;

    for (int t = 0; t < ntiles; ++t) {
        const int stg = t & 1;
        if (t + 1 < ntiles) {
            load_kv(t + 1, stg ^ 1);
            asm volatile("cp.async.wait_group 1;" ::: "memory");
        } else {
            asm volatile("cp.async.wait_group 0;" ::: "memory");
        }
        __syncthreads();

        const uint32_t kbase = sb + 2 * QARR + stg * KVSTG;

        // ---- S = Q K^T  (per-warp 16 x 64) ----
        float s[8][4];
#pragma unroll
        for (int ni = 0; ni < 8; ++ni)
#pragma unroll
            for (int q = 0; q < 4; ++q) s[ni][q] = 0.0f;

#pragma unroll
        for (int ks = 0; ks < 4; ++ks) {
#pragma unroll
            for (int nb = 0; nb < 4; ++nb) {
                const uint32_t adr = kbase
                    + (nb * 16 + (lane & 7) + 8 * (lane >> 4)) * QROWB
                    + ((lane >> 3) & 1) * 16 + ks * 32;
                uint32_t t0, t1, t2, t3, u0, u1, u2, u3;
                ldsm_x4(adr,         t0, t1, t2, t3);
                ldsm_x4(adr + KARRA, u0, u1, u2, u3);
                uint32_t bh0[2] = {t0, t1}, bh1[2] = {t2, t3};
                uint32_t bl0[2] = {u0, u1}, bl1[2] = {u2, u3};
                mma16816(s[nb*2],   qfh[ks], bh0);
                mma16816(s[nb*2],   qfh[ks], bl0);
                mma16816(s[nb*2],   qfl[ks], bh0);
                mma16816(s[nb*2+1], qfh[ks], bh1);
                mma16816(s[nb*2+1], qfh[ks], bl1);
                mma16816(s[nb*2+1], qfl[ks], bh1);
            }
        }

        // ---- mask + online softmax (log2 domain) ----
        const int kv0 = t << 6;
        const int cb  = kv0 + 2 * (lane & 3);
        float tmax0 = -1e30f, tmax1 = -1e30f;
#pragma unroll
        for (int ni = 0; ni < 8; ++ni) {
            const int c0 = cb + 8 * ni;
            if (c0     >= len) { s[ni][0] = -1e30f; s[ni][2] = -1e30f; }
            if (c0 + 1 >= len) { s[ni][1] = -1e30f; s[ni][3] = -1e30f; }
            tmax0 = fmaxf(tmax0, fmaxf(s[ni][0], s[ni][1]));
            tmax1 = fmaxf(tmax1, fmaxf(s[ni][2], s[ni][3]));
        }
        tmax0 = fmaxf(tmax0, __shfl_xor_sync(0xffffffffu, tmax0, 1));
        tmax0 = fmaxf(tmax0, __shfl_xor_sync(0xffffffffu, tmax0, 2));
        tmax1 = fmaxf(tmax1, __shfl_xor_sync(0xffffffffu, tmax1, 1));
        tmax1 = fmaxf(tmax1, __shfl_xor_sync(0xffffffffu, tmax1, 2));

        const float mn0 = fmaxf(m0r, tmax0);
        const float mn1 = fmaxf(m1r, tmax1);
        const float sc0 = ex2(m0r - mn0);
        const float sc1 = ex2(m1r - mn1);
        m0r = mn0; m1r = mn1;

        float ps0 = 0.0f, ps1 = 0.0f;
#pragma unroll
        for (int ni = 0; ni < 8; ++ni) {
            float p0 = ex2(s[ni][0] - mn0);
            float p1 = ex2(s[ni][1] - mn0);
            float p2 = ex2(s[ni][2] - mn1);
            float p3 = ex2(s[ni][3] - mn1);
            ps0 += p0 + p1;
            ps1 += p2 + p3;
            __nv_bfloat16 h0 = __float2bfloat16_rn(p0);
            __nv_bfloat16 h1 = __float2bfloat16_rn(p1);
            __nv_bfloat16 h2 = __float2bfloat16_rn(p2);
            __nv_bfloat16 h3 = __float2bfloat16_rn(p3);
            s[ni][0] = __uint_as_float(pack_bf2(__bfloat162float(h0), __bfloat162float(h1)));
            s[ni][1] = __uint_as_float(pack_bf2(p0 - __bfloat162float(h0),
                                                p1 - __bfloat162float(h1)));
            s[ni][2] = __uint_as_float(pack_bf2(__bfloat162float(h2), __bfloat162float(h3)));
            s[ni][3] = __uint_as_float(pack_bf2(p2 - __bfloat162float(h2),
                                                p3 - __bfloat162float(h3)));
        }
        ps0 += __shfl_xor_sync(0xffffffffu, ps0, 1);
        ps0 += __shfl_xor_sync(0xffffffffu, ps0, 2);
        ps1 += __shfl_xor_sync(0xffffffffu, ps1, 1);
        ps1 += __shfl_xor_sync(0xffffffffu, ps1, 2);
        lsum0 = lsum0 * sc0 + ps0;
        lsum1 = lsum1 * sc1 + ps1;
#pragma unroll
        for (int di = 0; di < 8; ++di) {
            o[di][0] *= sc0; o[di][1] *= sc0;
            o[di][2] *= sc1; o[di][3] *= sc1;
        }

        // ---- O += P V ----
        const uint32_t vbase = kbase + 2 * KARRA;
#pragma unroll
        for (int ks2 = 0; ks2 < 4; ++ks2) {
            uint32_t Ahf[4] = {
                __float_as_uint(s[2*ks2][0]),   __float_as_uint(s[2*ks2][2]),
                __float_as_uint(s[2*ks2+1][0]), __float_as_uint(s[2*ks2+1][2]) };
            uint32_t Alf[4] = {
                __float_as_uint(s[2*ks2][1]),   __float_as_uint(s[2*ks2][3]),
                __float_as_uint(s[2*ks2+1][1]), __float_as_uint(s[2*ks2+1][3]) };
#pragma unroll
            for (int db = 0; db < 4; ++db) {
                const uint32_t adr = vbase
                    + (ks2 * 16 + (lane & 7) + 8 * ((lane >> 3) & 1)) * QROWB
                    + ((lane >> 4) & 1) * 16 + db * 32;
                uint32_t t0, t1, t2, t3, u0, u1, u2, u3;
                ldsm_x4_t(adr,         t0, t1, t2, t3);
                ldsm_x4_t(adr + KARRA, u0, u1, u2, u3);
                uint32_t vh0[2] = {t0, t1}, vh1[2] = {t2, t3};
                uint32_t vl0[2] = {u0, u1}, vl1[2] = {u2, u3};
                mma16816(o[db*2],   Ahf, vh0);
                mma16816(o[db*2],   Ahf, vl0);
                mma16816(o[db*2],   Alf, vh0);
                mma16816(o[db*2+1], Ahf, vh1);
                mma16816(o[db*2+1], Ahf, vl1);
                mma16816(o[db*2+1], Alf, vh1);
            }
        }
        __syncthreads();
    }

    // ---- normalize + write ctx bf16 hi/lo [B,S,D] ----
    const float inv0 = 1.0f / lsum0;
    const float inv1 = 1.0f / lsum1;
    const int r  = lane >> 2;
    const int dc = 2 * (lane & 3);
    const int qrow0 = q0 + wid * 16 + r;
#pragma unroll
    for (int di = 0; di < 8; ++di) {
        const int d = 8 * di + dc;
        {
            const int idx = ((b * NS + qrow0) * ND) + h * NDH + d;
            float v0 = o[di][0] * inv0, v1 = o[di][1] * inv0;
            __nv_bfloat16 h0 = __float2bfloat16_rn(v0);
            __nv_bfloat16 h1 = __float2bfloat16_rn(v1);
            *(uint32_t*)&ch[idx] = pack_bf2(__bfloat162float(h0), __bfloat162float(h1));
            *(uint32_t*)&cl[idx] = pack_bf2(v0 - __bfloat162float(h0), v1 - __bfloat162float(h1));
        }
        {
            const int idx = ((b * NS + qrow0 + 8) * ND) + h * NDH + d;
            float v0 = o[di][2] * inv1, v1 = o[di][3] * inv1;
            __nv_bfloat16 h0 = __float2bfloat16_rn(v0);
            __nv_bfloat16 h1 = __float2bfloat16_rn(v1);
            *(uint32_t*)&ch[idx] = pack_bf2(__bfloat162float(h0), __bfloat162float(h1));
            *(uint32_t*)&cl[idx] = pack_bf2(v0 - __bfloat162float(h0), v1 - __bfloat162float(h1));
        }
    }
}

// ---------------------------------------------------------------------------
extern "C" void kernel_launch(void* const* d_in, const int* in_sizes, int n_in,
                              void* d_out, int out_size)
{
    (void)in_sizes; (void)n_in; (void)out_size;
    const float* Q  = (const float*)d_in[0];
    const float* K  = (const float*)d_in[1];
    const float* V  = (const float*)d_in[2];
    const float* Wq = (const float*)d_in[3];
    const float* bq = (const float*)d_in[4];
    const float* Wk = (const float*)d_in[5];
    const float* bk = (const float*)d_in[6];
    const float* Wv = (const float*)d_in[7];
    const float* bv = (const float*)d_in[8];
    const float* Wo = (const float*)d_in[9];
    const float* bo = (const float*)d_in[10];
    const void*  mk = d_in[11];
    float* out = (float*)d_out;

    __nv_bfloat16 *pqh, *pql, *pkh, *pkl, *pvh, *pvl, *pch, *pcl;
    __nv_bfloat16 *pah, *pal, *pwh, *pwl;
    cudaGetSymbolAddress((void**)&pqh, g_qh);
    cudaGetSymbolAddress((void**)&pql, g_ql);
    cudaGetSymbolAddress((void**)&pkh, g_kh);
    cudaGetSymbolAddress((void**)&pkl, g_kl);
    cudaGetSymbolAddress((void**)&pvh, g_vh);
    cudaGetSymbolAddress((void**)&pvl, g_vl);
    cudaGetSymbolAddress((void**)&pch, g_ch);
    cudaGetSymbolAddress((void**)&pcl, g_cl);
    cudaGetSymbolAddress((void**)&pah, g_ah);
    cudaGetSymbolAddress((void**)&pal, g_al);
    cudaGetSymbolAddress((void**)&pwh, g_wh);
    cudaGetSymbolAddress((void**)&pwl, g_wl);

    const int NACT = NB * NS * ND;
    const int NW   = ND * ND;

    cudaFuncSetAttribute(proj_hmma<1>, cudaFuncAttributeMaxDynamicSharedMemorySize, PROJ_SMEM);
    cudaFuncSetAttribute(proj_hmma<0>, cudaFuncAttributeMaxDynamicSharedMemorySize, PROJ_SMEM);
    cudaFuncSetAttribute(attn_hmma, cudaFuncAttributeMaxDynamicSharedMemorySize, ATTN_SMEM);

    const float QSCALE = 0.125f * 1.4426950408889634f;  // 1/sqrt(64) * log2(e)

    // 1) all 4 weight splits in one launch
    {
        ConvArgs ca;
        ca.in[0] = Wq; ca.in[1] = Wk; ca.in[2] = Wv; ca.in[3] = Wo;
        for (int i = 0; i < 4; ++i) { ca.hi[i] = pwh + i * NW; ca.lo[i] = pwl + i * NW; }
        ca.n4 = NW / 4;
        conv_multi<<<dim3((NW / 4 + 255) / 256, 4), 256>>>(ca);
    }
    // 2) Q,K,V activation splits in one launch
    {
        ConvArgs ca;
        ca.in[0] = Q; ca.in[1] = K; ca.in[2] = V; ca.in[3] = Q;
        for (int i = 0; i < 4; ++i) {
            int j = (i < 3) ? i : 0;
            ca.hi[i] = pah + j * NACT; ca.lo[i] = pal + j * NACT;
        }
        ca.n4 = NACT / 4;
        conv_multi<<<dim3((NACT / 4 + 255) / 256, 3), 256>>>(ca);
    }
    // 3) fused Q/K/V projections
    {
        ProjArgs pa;
        for (int i = 0; i < 3; ++i) {
            pa.Ah[i] = pah + i * NACT; pa.Al[i] = pal + i * NACT;
            pa.Bh[i] = pwh + i * NW;   pa.Bl[i] = pwl + i * NW;
        }
        pa.bias[0] = bq; pa.bias[1] = bk; pa.bias[2] = bv;
        pa.oH[0] = pqh; pa.oL[0] = pql;
        pa.oH[1] = pkh; pa.oL[1] = pkl;
        pa.oH[2] = pvh; pa.oL[2] = pvl;
        pa.oF = nullptr;
        pa.scale[0] = QSCALE; pa.scale[1] = 1.0f; pa.scale[2] = 1.0f;
        proj_hmma<1><<<dim3(64, 4, 3), 256, PROJ_SMEM>>>(pa);
    }
    // 4) attention (256 q rows per CTA, 512 threads)
    attn_hmma<<<dim3(NS / 256, NB * NH), 512, ATTN_SMEM>>>(
        pqh, pql, pkh, pkl, pvh, pvl, pch, pcl, mk);
    // 5) output projection
    {
        ProjArgs pa;
        pa.Ah[0] = pch; pa.Al[0] = pcl;
        pa.Bh[0] = pwh + 3 * NW; pa.Bl[0] = pwl + 3 * NW;
        pa.bias[0] = bo;
        pa.oH[0] = nullptr; pa.oL[0] = nullptr;
        pa.oF = out;
        pa.scale[0] = 1.0f;
        pa.Ah[1] = pa.Ah[2] = pch; pa.Al[1] = pa.Al[2] = pcl;
        pa.Bh[1] = pa.Bh[2] = pwh; pa.Bl[1] = pa.Bl[2] = pwl;
        pa.bias[1] = pa.bias[2] = bo;
        pa.oH[1] = pa.oH[2] = nullptr; pa.oL[1] = pa.oL[2] = nullptr;
        pa.scale[1] = pa.scale[2] = 1.0f;
        proj_hmma<0><<<dim3(64, 4, 1), 256, PROJ_SMEM>>>(pa);
    }
}

// round 7
// speedup vs baseline: 1.4838x; 1.4838x over previous
#include <cuda_runtime.h>
#include <cuda_fp16.h>
#include <cstdint>

#define NB  4
#define NS  2048
#define ND  512
#define NH  8
#define NDH 64

// ---------------------------------------------------------------------------
// Scratch (device globals: allocation-free rule)
// ---------------------------------------------------------------------------
__device__ __half g_qh[NB * NH * NS * NDH];
__device__ __half g_ql[NB * NH * NS * NDH];
__device__ __half g_kh[NB * NH * NS * NDH];   // hi only (B-side of QK^T)
__device__ __half g_vh[NB * NH * NS * NDH];   // hi only (B-side of PV)
__device__ __half g_ch[NB * NS * ND];         // ctx hi
__device__ __half g_cl[NB * NS * ND];         // ctx lo
__device__ __half g_ah[NB * NS * ND];         // activation hi (reused per proj)
__device__ __half g_al[NB * NS * ND];         // activation lo
__device__ __half g_wh[ND * ND];              // weight hi only (B-side)

// ---------------------------------------------------------------------------
__device__ __forceinline__ uint32_t smem_u32(const void* p) {
    uint32_t a;
    asm("{ .reg .u64 t; cvta.to.shared.u64 t, %1; cvt.u32.u64 %0, t; }"
        : "=r"(a) : "l"(p));
    return a;
}
__device__ __forceinline__ void cp_async16(uint32_t dst, const void* src) {
    asm volatile("cp.async.ca.shared.global [%0], [%1], 16;"
                 :: "r"(dst), "l"(src) : "memory");
}
__device__ __forceinline__ void cp_commit() {
    asm volatile("cp.async.commit_group;" ::: "memory");
}
__device__ __forceinline__ void ldsm_x4(uint32_t addr, uint32_t& r0, uint32_t& r1,
                                        uint32_t& r2, uint32_t& r3) {
    asm volatile("ldmatrix.sync.aligned.m8n8.x4.shared.b16 {%0,%1,%2,%3}, [%4];"
                 : "=r"(r0), "=r"(r1), "=r"(r2), "=r"(r3) : "r"(addr));
}
__device__ __forceinline__ void ldsm_x4_t(uint32_t addr, uint32_t& r0, uint32_t& r1,
                                          uint32_t& r2, uint32_t& r3) {
    asm volatile("ldmatrix.sync.aligned.m8n8.x4.trans.shared.b16 {%0,%1,%2,%3}, [%4];"
                 : "=r"(r0), "=r"(r1), "=r"(r2), "=r"(r3) : "r"(addr));
}
__device__ __forceinline__ void mma16816(float* c, const uint32_t* a, const uint32_t* b) {
    asm volatile(
        "mma.sync.aligned.m16n8k16.row.col.f32.f16.f16.f32 "
        "{%0,%1,%2,%3}, {%4,%5,%6,%7}, {%8,%9}, {%0,%1,%2,%3};"
        : "+f"(c[0]), "+f"(c[1]), "+f"(c[2]), "+f"(c[3])
        : "r"(a[0]), "r"(a[1]), "r"(a[2]), "r"(a[3]), "r"(b[0]), "r"(b[1]));
}
__device__ __forceinline__ float ex2(float x) {
    float y;
    asm("ex2.approx.ftz.f32 %0, %1;" : "=f"(y) : "f"(x));
    return y;
}
__device__ __forceinline__ uint32_t pack_h2(float a, float b) {
    __half2 t = __floats2half2_rn(a, b);
    return *(uint32_t*)&t;
}

// ---------------------------------------------------------------------------
// fp32 -> fp16 conversions
// ---------------------------------------------------------------------------
__global__ __launch_bounds__(256) void conv_hl(
    const float* __restrict__ in, __half* __restrict__ hi,
    __half* __restrict__ lo, int n4)
{
    int idx = blockIdx.x * 256 + threadIdx.x;
    if (idx >= n4) return;
    float4 v = ((const float4*)in)[idx];
    float f[4] = {v.x, v.y, v.z, v.w};
    __half h[4], l[4];
#pragma unroll
    for (int i = 0; i < 4; ++i) {
        h[i] = __float2half_rn(f[i]);
        l[i] = __float2half_rn(f[i] - __half2float(h[i]));
    }
    ((uint2*)hi)[idx] = *(uint2*)h;
    ((uint2*)lo)[idx] = *(uint2*)l;
}

__global__ __launch_bounds__(256) void conv_h(
    const float* __restrict__ in, __half* __restrict__ hi, int n4)
{
    int idx = blockIdx.x * 256 + threadIdx.x;
    if (idx >= n4) return;
    float4 v = ((const float4*)in)[idx];
    float f[4] = {v.x, v.y, v.z, v.w};
    __half h[4];
#pragma unroll
    for (int i = 0; i < 4; ++i) h[i] = __float2half_rn(f[i]);
    ((uint2*)hi)[idx] = *(uint2*)h;
}

// ---------------------------------------------------------------------------
// HMMA projection GEMM: C[8192,512] = X @ W^T + bias
// fp16, 2 products: Ah*Bh + Al*Bh (B stored hi-only).
// MODE 0: fp32 row-major out. MODE 1: fp16 hi(/lo) out, head layout, scaled.
// ---------------------------------------------------------------------------
#define ROWB   80
#define ARRSZ  10240
#define STAGESZ (3 * ARRSZ)
#define PROJ_SMEM (2 * STAGESZ)   // 61440

template <int MODE>
__global__ __launch_bounds__(256) void proj_hmma(
    const __half* __restrict__ Ah, const __half* __restrict__ Al,
    const __half* __restrict__ Bh,
    const float* __restrict__ bias, float* __restrict__ outF,
    __half* __restrict__ outH, __half* __restrict__ outL, float scale)
{
    extern __shared__ char smem[];
    const uint32_t sb = smem_u32(smem);
    const int tid  = threadIdx.x;
    const int lane = tid & 31;
    const int wid  = tid >> 5;
    const int warp_m = wid & 3;
    const int warp_n = wid >> 2;
    const int m0 = blockIdx.x * 128;
    const int n0 = blockIdx.y * 128;

    const int r0c = (tid + 0)   >> 2, s0c = tid & 3;
    const int r1c = (tid + 256) >> 2, s1c = tid & 3;

    const uint32_t a_off = (uint32_t)((warp_m * 32 + (lane & 15)) * ROWB + (lane >> 4) * 16);
    const uint32_t b_off = (uint32_t)((warp_n * 64 + (lane & 7) + 8 * (lane >> 4)) * ROWB
                                      + ((lane >> 3) & 1) * 16);

    float acc[2][8][4];
#pragma unroll
    for (int mi = 0; mi < 2; ++mi)
#pragma unroll
        for (int ni = 0; ni < 8; ++ni)
#pragma unroll
            for (int q = 0; q < 4; ++q) acc[mi][ni][q] = 0.0f;

    auto load_chunk = [&](int c, int stage) {
        const int k0 = c * 32;
        const uint32_t st = sb + stage * STAGESZ;
        const __half* srcs[3] = {Ah, Al, Bh};
#pragma unroll
        for (int arr = 0; arr < 3; ++arr) {
            const __half* base = srcs[arr];
            const int rbase = (arr < 2) ? m0 : n0;
            cp_async16(st + arr * ARRSZ + r0c * ROWB + s0c * 16,
                       base + (rbase + r0c) * ND + k0 + s0c * 8);
            cp_async16(st + arr * ARRSZ + r1c * ROWB + s1c * 16,
                       base + (rbase + r1c) * ND + k0 + s1c * 8);
        }
        cp_commit();
    };

    load_chunk(0, 0);

    for (int c = 0; c < 16; ++c) {
        const int stage = c & 1;
        if (c < 15) {
            load_chunk(c + 1, stage ^ 1);
            asm volatile("cp.async.wait_group 1;" ::: "memory");
        } else {
            asm volatile("cp.async.wait_group 0;" ::: "memory");
        }
        __syncthreads();

        const uint32_t st = sb + stage * STAGESZ;
#pragma unroll
        for (int ks = 0; ks < 2; ++ks) {
            const uint32_t kb = ks * 32;
            uint32_t ah[2][4], al[2][4];
#pragma unroll
            for (int mi = 0; mi < 2; ++mi) {
                uint32_t adr = st + a_off + mi * (16 * ROWB) + kb;
                ldsm_x4(adr,         ah[mi][0], ah[mi][1], ah[mi][2], ah[mi][3]);
                ldsm_x4(adr + ARRSZ, al[mi][0], al[mi][1], al[mi][2], al[mi][3]);
            }
            uint32_t bh[8][2];
#pragma unroll
            for (int nb = 0; nb < 4; ++nb) {
                uint32_t adr = st + 2 * ARRSZ + b_off + nb * (16 * ROWB) + kb;
                uint32_t t0, t1, t2, t3;
                ldsm_x4(adr, t0, t1, t2, t3);
                bh[nb*2][0] = t0; bh[nb*2][1] = t1; bh[nb*2+1][0] = t2; bh[nb*2+1][1] = t3;
            }
#pragma unroll
            for (int mi = 0; mi < 2; ++mi)
#pragma unroll
                for (int ni = 0; ni < 8; ++ni) {
                    mma16816(acc[mi][ni], ah[mi], bh[ni]);
                    mma16816(acc[mi][ni], al[mi], bh[ni]);
                }
        }
        __syncthreads();
    }

    const int crow = lane >> 2;
    const int ccol = (lane & 3) * 2;
#pragma unroll
    for (int mi = 0; mi < 2; ++mi) {
#pragma unroll
        for (int half = 0; half < 2; ++half) {
            const int m = m0 + warp_m * 32 + mi * 16 + crow + half * 8;
            const int b = m >> 11, s = m & 2047;
#pragma unroll
            for (int ni = 0; ni < 8; ++ni) {
                const int n = n0 + warp_n * 64 + ni * 8 + ccol;
                float v0 = acc[mi][ni][half * 2 + 0] + bias[n];
                float v1 = acc[mi][ni][half * 2 + 1] + bias[n + 1];
                if (MODE == 1) {
                    v0 *= scale; v1 *= scale;
                    const int head = n >> 6, d = n & 63;
                    const int idx = ((b * NH + head) * NS + s) * NDH + d;
                    __half h0 = __float2half_rn(v0);
                    __half h1 = __float2half_rn(v1);
                    *(uint32_t*)&outH[idx] =
                        pack_h2(__half2float(h0), __half2float(h1));
                    if (outL) {
                        *(uint32_t*)&outL[idx] =
                            pack_h2(v0 - __half2float(h0), v1 - __half2float(h1));
                    }
                } else {
                    *(float2*)&outF[m * ND + n] = make_float2(v0, v1);
                }
            }
        }
    }
}

// ---------------------------------------------------------------------------
// HMMA flash attention (fp16, 2-product). CTA = 128 q rows x one (b,h),
// 8 warps x 16 rows, KV tile 128 double-buffered. q hi/lo (A-side),
// k/v hi only. q pre-scaled by 0.125*log2(e); softmax in log2 domain.
// ---------------------------------------------------------------------------
#define QROWB 144
#define QARR  18432            // 128 rows x 144B
#define KVSTG (2 * QARR)       // Kh + Vh per stage
#define ATTN_SMEM (2 * QARR + 2 * KVSTG)   // 110592

__global__ __launch_bounds__(256) void attn_hmma(
    const __half* __restrict__ qh, const __half* __restrict__ ql,
    const __half* __restrict__ kh, const __half* __restrict__ vh,
    __half* __restrict__ ch, __half* __restrict__ cl,
    const void* __restrict__ masked_raw)
{
    extern __shared__ char smem[];
    const uint32_t sb = smem_u32(smem);
    const int tid  = threadIdx.x;
    const int lane = tid & 31;
    const int wid  = tid >> 5;
    const int bh   = blockIdx.y;
    const int b    = bh >> 3;
    const int h    = bh & 7;
    const int q0   = blockIdx.x << 7;
    const int gbase = bh * NS * NDH;

    int len;
    {
        const long long* ml = (const long long*)masked_raw;
        long long probe = ml[0];
        if (probe >= 1 && probe <= NS) len = (int)ml[b];
        else                           len = ((const int*)masked_raw)[b];
    }
    const int ntiles = (len + 127) >> 7;

    // Load Q hi/lo into smem
#pragma unroll
    for (int i = 0; i < 4; ++i) {
        int c = tid + i * 256;
        int r = c >> 3, blk = c & 7;
        const int src = gbase + (q0 + r) * NDH + blk * 8;
        *(uint4*)(smem + r * QROWB + blk * 16)        = *(const uint4*)(qh + src);
        *(uint4*)(smem + QARR + r * QROWB + blk * 16) = *(const uint4*)(ql + src);
    }

    auto load_kv = [&](int t, int stg) {
        const uint32_t s0 = sb + 2 * QARR + stg * KVSTG;
        const int gk = gbase + (t << 7) * NDH;
#pragma unroll
        for (int i = 0; i < 4; ++i) {
            int c = tid + i * 256;
            int r = c >> 3, blk = c & 7;
            const uint32_t dst = s0 + r * QROWB + blk * 16;
            const int src = gk + r * NDH + blk * 8;
            cp_async16(dst,        kh + src);
            cp_async16(dst + QARR, vh + src);
        }
        cp_commit();
    };

    load_kv(0, 0);
    __syncthreads();   // Q smem ready

    uint32_t qfh[4][4], qfl[4][4];
    {
        const uint32_t qa = sb + (wid * 16 + (lane & 15)) * QROWB + (lane >> 4) * 16;
#pragma unroll
        for (int ks = 0; ks < 4; ++ks) {
            ldsm_x4(qa + ks * 32,        qfh[ks][0], qfh[ks][1], qfh[ks][2], qfh[ks][3]);
            ldsm_x4(qa + ks * 32 + QARR, qfl[ks][0], qfl[ks][1], qfl[ks][2], qfl[ks][3]);
        }
    }

    float m0r = -1e30f, m1r = -1e30f, lsum0 = 0.0f, lsum1 = 0.0f;
    float o[8][4];
#pragma unroll
    for (int di = 0; di < 8; ++di)
#pragma unroll
        for (int q = 0; q < 4; ++q) o[di][q] = 0.0f;

    for (int t = 0; t < ntiles; ++t) {
        const int stg = t & 1;
        if (t + 1 < ntiles) {
            load_kv(t + 1, stg ^ 1);
            asm volatile("cp.async.wait_group 1;" ::: "memory");
        } else {
            asm volatile("cp.async.wait_group 0;" ::: "memory");
        }
        __syncthreads();

        const uint32_t kbase = sb + 2 * QARR + stg * KVSTG;

        // ---- S = Q K^T  (per-warp 16 x 128) ----
        float s[16][4];
#pragma unroll
        for (int ni = 0; ni < 16; ++ni)
#pragma unroll
            for (int q = 0; q < 4; ++q) s[ni][q] = 0.0f;

#pragma unroll
        for (int ks = 0; ks < 4; ++ks) {
#pragma unroll
            for (int nb = 0; nb < 8; ++nb) {
                const uint32_t adr = kbase
                    + (nb * 16 + (lane & 7) + 8 * (lane >> 4)) * QROWB
                    + ((lane >> 3) & 1) * 16 + ks * 32;
                uint32_t t0, t1, t2, t3;
                ldsm_x4(adr, t0, t1, t2, t3);
                uint32_t bh0[2] = {t0, t1}, bh1[2] = {t2, t3};
                mma16816(s[nb*2],   qfh[ks], bh0);
                mma16816(s[nb*2],   qfl[ks], bh0);
                mma16816(s[nb*2+1], qfh[ks], bh1);
                mma16816(s[nb*2+1], qfl[ks], bh1);
            }
        }

        // ---- mask + online softmax (log2 domain) ----
        const int kv0 = t << 7;
        const int cb  = kv0 + 2 * (lane & 3);
        float tmax0 = -1e30f, tmax1 = -1e30f;
#pragma unroll
        for (int ni = 0; ni < 16; ++ni) {
            const int c0 = cb + 8 * ni;
            if (c0     >= len) { s[ni][0] = -1e30f; s[ni][2] = -1e30f; }
            if (c0 + 1 >= len) { s[ni][1] = -1e30f; s[ni][3] = -1e30f; }
            tmax0 = fmaxf(tmax0, fmaxf(s[ni][0], s[ni][1]));
            tmax1 = fmaxf(tmax1, fmaxf(s[ni][2], s[ni][3]));
        }
        tmax0 = fmaxf(tmax0, __shfl_xor_sync(0xffffffffu, tmax0, 1));
        tmax0 = fmaxf(tmax0, __shfl_xor_sync(0xffffffffu, tmax0, 2));
        tmax1 = fmaxf(tmax1, __shfl_xor_sync(0xffffffffu, tmax1, 1));
        tmax1 = fmaxf(tmax1, __shfl_xor_sync(0xffffffffu, tmax1, 2));

        const float mn0 = fmaxf(m0r, tmax0);
        const float mn1 = fmaxf(m1r, tmax1);
        const float sc0 = ex2(m0r - mn0);
        const float sc1 = ex2(m1r - mn1);
        m0r = mn0; m1r = mn1;

        float ps0 = 0.0f, ps1 = 0.0f;
        // P packed hi/lo in place of s: [0]=ph rowA, [1]=pl rowA, [2]=ph rowB, [3]=pl rowB
#pragma unroll
        for (int ni = 0; ni < 16; ++ni) {
            float p0 = ex2(s[ni][0] - mn0);
            float p1 = ex2(s[ni][1] - mn0);
            float p2 = ex2(s[ni][2] - mn1);
            float p3 = ex2(s[ni][3] - mn1);
            ps0 += p0 + p1;
            ps1 += p2 + p3;
            __half h0 = __float2half_rn(p0);
            __half h1 = __float2half_rn(p1);
            __half h2 = __float2half_rn(p2);
            __half h3 = __float2half_rn(p3);
            s[ni][0] = __uint_as_float(pack_h2(__half2float(h0), __half2float(h1)));
            s[ni][1] = __uint_as_float(pack_h2(p0 - __half2float(h0),
                                               p1 - __half2float(h1)));
            s[ni][2] = __uint_as_float(pack_h2(__half2float(h2), __half2float(h3)));
            s[ni][3] = __uint_as_float(pack_h2(p2 - __half2float(h2),
                                               p3 - __half2float(h3)));
        }
        ps0 += __shfl_xor_sync(0xffffffffu, ps0, 1);
        ps0 += __shfl_xor_sync(0xffffffffu, ps0, 2);
        ps1 += __shfl_xor_sync(0xffffffffu, ps1, 1);
        ps1 += __shfl_xor_sync(0xffffffffu, ps1, 2);
        lsum0 = lsum0 * sc0 + ps0;
        lsum1 = lsum1 * sc1 + ps1;
#pragma unroll
        for (int di = 0; di < 8; ++di) {
            o[di][0] *= sc0; o[di][1] *= sc0;
            o[di][2] *= sc1; o[di][3] *= sc1;
        }

        // ---- O += P V  (V hi only) ----
        const uint32_t vbase = kbase + QARR;
#pragma unroll
        for (int ks2 = 0; ks2 < 8; ++ks2) {
            uint32_t Ahf[4] = {
                __float_as_uint(s[2*ks2][0]),   __float_as_uint(s[2*ks2][2]),
                __float_as_uint(s[2*ks2+1][0]), __float_as_uint(s[2*ks2+1][2]) };
            uint32_t Alf[4] = {
                __float_as_uint(s[2*ks2][1]),   __float_as_uint(s[2*ks2][3]),
                __float_as_uint(s[2*ks2+1][1]), __float_as_uint(s[2*ks2+1][3]) };
#pragma unroll
            for (int db = 0; db < 4; ++db) {
                const uint32_t adr = vbase
                    + (ks2 * 16 + (lane & 7) + 8 * ((lane >> 3) & 1)) * QROWB
                    + ((lane >> 4) & 1) * 16 + db * 32;
                uint32_t t0, t1, t2, t3;
                ldsm_x4_t(adr, t0, t1, t2, t3);
                uint32_t vh0[2] = {t0, t1}, vh1[2] = {t2, t3};
                mma16816(o[db*2],   Ahf, vh0);
                mma16816(o[db*2],   Alf, vh0);
                mma16816(o[db*2+1], Ahf, vh1);
                mma16816(o[db*2+1], Alf, vh1);
            }
        }
        __syncthreads();
    }

    // ---- normalize + write ctx fp16 hi/lo [B,S,D] ----
    const float inv0 = 1.0f / lsum0;
    const float inv1 = 1.0f / lsum1;
    const int r  = lane >> 2;
    const int dc = 2 * (lane & 3);
    const int qrow0 = q0 + wid * 16 + r;
#pragma unroll
    for (int di = 0; di < 8; ++di) {
        const int d = 8 * di + dc;
        {
            const int idx = ((b * NS + qrow0) * ND) + h * NDH + d;
            float v0 = o[di][0] * inv0, v1 = o[di][1] * inv0;
            __half h0 = __float2half_rn(v0);
            __half h1 = __float2half_rn(v1);
            *(uint32_t*)&ch[idx] = pack_h2(__half2float(h0), __half2float(h1));
            *(uint32_t*)&cl[idx] = pack_h2(v0 - __half2float(h0), v1 - __half2float(h1));
        }
        {
            const int idx = ((b * NS + qrow0 + 8) * ND) + h * NDH + d;
            float v0 = o[di][2] * inv1, v1 = o[di][3] * inv1;
            __half h0 = __float2half_rn(v0);
            __half h1 = __float2half_rn(v1);
            *(uint32_t*)&ch[idx] = pack_h2(__half2float(h0), __half2float(h1));
            *(uint32_t*)&cl[idx] = pack_h2(v0 - __half2float(h0), v1 - __half2float(h1));
        }
    }
}

// ---------------------------------------------------------------------------
extern "C" void kernel_launch(void* const* d_in, const int* in_sizes, int n_in,
                              void* d_out, int out_size)
{
    (void)in_sizes; (void)n_in; (void)out_size;
    const float* Q  = (const float*)d_in[0];
    const float* K  = (const float*)d_in[1];
    const float* V  = (const float*)d_in[2];
    const float* Wq = (const float*)d_in[3];
    const float* bq = (const float*)d_in[4];
    const float* Wk = (const float*)d_in[5];
    const float* bk = (const float*)d_in[6];
    const float* Wv = (const float*)d_in[7];
    const float* bv = (const float*)d_in[8];
    const float* Wo = (const float*)d_in[9];
    const float* bo = (const float*)d_in[10];
    const void*  mk = d_in[11];
    float* out = (float*)d_out;

    __half *pqh, *pql, *pkh, *pvh, *pch, *pcl, *pah, *pal, *pwh;
    cudaGetSymbolAddress((void**)&pqh, g_qh);
    cudaGetSymbolAddress((void**)&pql, g_ql);
    cudaGetSymbolAddress((void**)&pkh, g_kh);
    cudaGetSymbolAddress((void**)&pvh, g_vh);
    cudaGetSymbolAddress((void**)&pch, g_ch);
    cudaGetSymbolAddress((void**)&pcl, g_cl);
    cudaGetSymbolAddress((void**)&pah, g_ah);
    cudaGetSymbolAddress((void**)&pal, g_al);
    cudaGetSymbolAddress((void**)&pwh, g_wh);

    const int nx4 = (NB * NS * ND) / 4;
    const int nw4 = (ND * ND) / 4;

    cudaFuncSetAttribute(proj_hmma<1>, cudaFuncAttributeMaxDynamicSharedMemorySize, PROJ_SMEM);
    cudaFuncSetAttribute(proj_hmma<0>, cudaFuncAttributeMaxDynamicSharedMemorySize, PROJ_SMEM);
    cudaFuncSetAttribute(attn_hmma, cudaFuncAttributeMaxDynamicSharedMemorySize, ATTN_SMEM);

    dim3 gp(64, 4);
    const float QSCALE = 0.125f * 1.4426950408889634f;  // 1/sqrt(64) * log2(e)

    // Q projection
    conv_h <<<(nw4 + 255) / 256, 256>>>(Wq, pwh, nw4);
    conv_hl<<<(nx4 + 255) / 256, 256>>>(Q, pah, pal, nx4);
    proj_hmma<1><<<gp, 256, PROJ_SMEM>>>(pah, pal, pwh, bq, nullptr, pqh, pql, QSCALE);
    // K projection (hi only)
    conv_h <<<(nw4 + 255) / 256, 256>>>(Wk, pwh, nw4);
    conv_hl<<<(nx4 + 255) / 256, 256>>>(K, pah, pal, nx4);
    proj_hmma<1><<<gp, 256, PROJ_SMEM>>>(pah, pal, pwh, bk, nullptr, pkh, nullptr, 1.0f);
    // V projection (hi only)
    conv_h <<<(nw4 + 255) / 256, 256>>>(Wv, pwh, nw4);
    conv_hl<<<(nx4 + 255) / 256, 256>>>(V, pah, pal, nx4);
    proj_hmma<1><<<gp, 256, PROJ_SMEM>>>(pah, pal, pwh, bv, nullptr, pvh, nullptr, 1.0f);

    // Attention
    attn_hmma<<<dim3(NS / 128, NB * NH), 256, ATTN_SMEM>>>(
        pqh, pql, pkh, pvh, pch, pcl, mk);

    // Output projection
    conv_h<<<(nw4 + 255) / 256, 256>>>(Wo, pwh, nw4);
    proj_hmma<0><<<gp, 256, PROJ_SMEM>>>(pch, pcl, pwh, bo, out, nullptr, nullptr, 1.0f);
}

// round 8
// speedup vs baseline: 1.5245x; 1.0275x over previous
#include <cuda_runtime.h>
#include <cuda_fp16.h>
#include <cstdint>

#define NB  4
#define NS  2048
#define ND  512
#define NH  8
#define NDH 64

// ---------------------------------------------------------------------------
// Scratch (device globals: allocation-free rule)
// ---------------------------------------------------------------------------
__device__ __half g_qh[NB * NH * NS * NDH];
__device__ __half g_ql[NB * NH * NS * NDH];
__device__ __half g_kh[NB * NH * NS * NDH];   // hi only (B-side of QK^T)
__device__ __half g_vh[NB * NH * NS * NDH];   // hi only (B-side of PV)
__device__ __half g_ch[NB * NS * ND];         // ctx hi
__device__ __half g_cl[NB * NS * ND];         // ctx lo
__device__ __half g_ah[NB * NS * ND];         // activation hi (reused per proj)
__device__ __half g_al[NB * NS * ND];         // activation lo
__device__ __half g_wh[ND * ND];              // weight hi only (B-side)

// ---------------------------------------------------------------------------
__device__ __forceinline__ uint32_t smem_u32(const void* p) {
    uint32_t a;
    asm("{ .reg .u64 t; cvta.to.shared.u64 t, %1; cvt.u32.u64 %0, t; }"
        : "=r"(a) : "l"(p));
    return a;
}
__device__ __forceinline__ void cp_async16(uint32_t dst, const void* src) {
    asm volatile("cp.async.ca.shared.global [%0], [%1], 16;"
                 :: "r"(dst), "l"(src) : "memory");
}
__device__ __forceinline__ void cp_commit() {
    asm volatile("cp.async.commit_group;" ::: "memory");
}
__device__ __forceinline__ void ldsm_x4(uint32_t addr, uint32_t& r0, uint32_t& r1,
                                        uint32_t& r2, uint32_t& r3) {
    asm volatile("ldmatrix.sync.aligned.m8n8.x4.shared.b16 {%0,%1,%2,%3}, [%4];"
                 : "=r"(r0), "=r"(r1), "=r"(r2), "=r"(r3) : "r"(addr));
}
__device__ __forceinline__ void ldsm_x4_t(uint32_t addr, uint32_t& r0, uint32_t& r1,
                                          uint32_t& r2, uint32_t& r3) {
    asm volatile("ldmatrix.sync.aligned.m8n8.x4.trans.shared.b16 {%0,%1,%2,%3}, [%4];"
                 : "=r"(r0), "=r"(r1), "=r"(r2), "=r"(r3) : "r"(addr));
}
__device__ __forceinline__ void mma16816(float* c, const uint32_t* a, const uint32_t* b) {
    asm volatile(
        "mma.sync.aligned.m16n8k16.row.col.f32.f16.f16.f32 "
        "{%0,%1,%2,%3}, {%4,%5,%6,%7}, {%8,%9}, {%0,%1,%2,%3};"
        : "+f"(c[0]), "+f"(c[1]), "+f"(c[2]), "+f"(c[3])
        : "r"(a[0]), "r"(a[1]), "r"(a[2]), "r"(a[3]), "r"(b[0]), "r"(b[1]));
}
__device__ __forceinline__ float ex2(float x) {
    float y;
    asm("ex2.approx.ftz.f32 %0, %1;" : "=f"(y) : "f"(x));
    return y;
}
__device__ __forceinline__ uint32_t pack_h2(float a, float b) {
    __half2 t = __floats2half2_rn(a, b);
    return *(uint32_t*)&t;
}

// ---------------------------------------------------------------------------
// fp32 -> fp16 conversions
// ---------------------------------------------------------------------------
__global__ __launch_bounds__(256) void conv_hl(
    const float* __restrict__ in, __half* __restrict__ hi,
    __half* __restrict__ lo, int n4)
{
    int idx = blockIdx.x * 256 + threadIdx.x;
    if (idx >= n4) return;
    float4 v = ((const float4*)in)[idx];
    float f[4] = {v.x, v.y, v.z, v.w};
    __half h[4], l[4];
#pragma unroll
    for (int i = 0; i < 4; ++i) {
        h[i] = __float2half_rn(f[i]);
        l[i] = __float2half_rn(f[i] - __half2float(h[i]));
    }
    ((uint2*)hi)[idx] = *(uint2*)h;
    ((uint2*)lo)[idx] = *(uint2*)l;
}

__global__ __launch_bounds__(256) void conv_h(
    const float* __restrict__ in, __half* __restrict__ hi, int n4)
{
    int idx = blockIdx.x * 256 + threadIdx.x;
    if (idx >= n4) return;
    float4 v = ((const float4*)in)[idx];
    float f[4] = {v.x, v.y, v.z, v.w};
    __half h[4];
#pragma unroll
    for (int i = 0; i < 4; ++i) h[i] = __float2half_rn(f[i]);
    ((uint2*)hi)[idx] = *(uint2*)h;
}

// ---------------------------------------------------------------------------
// HMMA projection GEMM: C[8192,512] = X @ W^T + bias
// fp16, 2 products: Ah*Bh + Al*Bh (B stored hi-only). 2 CTAs/SM.
// MODE 0: fp32 row-major out. MODE 1: fp16 hi(/lo) out, head layout, scaled.
// ---------------------------------------------------------------------------
#define ROWB   80
#define ARRSZ  10240
#define STAGESZ (3 * ARRSZ)
#define PROJ_SMEM (2 * STAGESZ)   // 61440

template <int MODE>
__global__ __launch_bounds__(256, 2) void proj_hmma(
    const __half* __restrict__ Ah, const __half* __restrict__ Al,
    const __half* __restrict__ Bh,
    const float* __restrict__ bias, float* __restrict__ outF,
    __half* __restrict__ outH, __half* __restrict__ outL, float scale)
{
    extern __shared__ char smem[];
    const uint32_t sb = smem_u32(smem);
    const int tid  = threadIdx.x;
    const int lane = tid & 31;
    const int wid  = tid >> 5;
    const int warp_m = wid & 3;
    const int warp_n = wid >> 2;
    const int m0 = blockIdx.x * 128;
    const int n0 = blockIdx.y * 128;

    const int r0c = (tid + 0)   >> 2, s0c = tid & 3;
    const int r1c = (tid + 256) >> 2, s1c = tid & 3;

    const uint32_t a_off = (uint32_t)((warp_m * 32 + (lane & 15)) * ROWB + (lane >> 4) * 16);
    const uint32_t b_off = (uint32_t)((warp_n * 64 + (lane & 7) + 8 * (lane >> 4)) * ROWB
                                      + ((lane >> 3) & 1) * 16);

    float acc[2][8][4];
#pragma unroll
    for (int mi = 0; mi < 2; ++mi)
#pragma unroll
        for (int ni = 0; ni < 8; ++ni)
#pragma unroll
            for (int q = 0; q < 4; ++q) acc[mi][ni][q] = 0.0f;

    auto load_chunk = [&](int c, int stage) {
        const int k0 = c * 32;
        const uint32_t st = sb + stage * STAGESZ;
        const __half* srcs[3] = {Ah, Al, Bh};
#pragma unroll
        for (int arr = 0; arr < 3; ++arr) {
            const __half* base = srcs[arr];
            const int rbase = (arr < 2) ? m0 : n0;
            cp_async16(st + arr * ARRSZ + r0c * ROWB + s0c * 16,
                       base + (rbase + r0c) * ND + k0 + s0c * 8);
            cp_async16(st + arr * ARRSZ + r1c * ROWB + s1c * 16,
                       base + (rbase + r1c) * ND + k0 + s1c * 8);
        }
        cp_commit();
    };

    load_chunk(0, 0);

    for (int c = 0; c < 16; ++c) {
        const int stage = c & 1;
        if (c < 15) {
            load_chunk(c + 1, stage ^ 1);
            asm volatile("cp.async.wait_group 1;" ::: "memory");
        } else {
            asm volatile("cp.async.wait_group 0;" ::: "memory");
        }
        __syncthreads();

        const uint32_t st = sb + stage * STAGESZ;
#pragma unroll
        for (int ks = 0; ks < 2; ++ks) {
            const uint32_t kb = ks * 32;
            uint32_t ah[2][4], al[2][4];
#pragma unroll
            for (int mi = 0; mi < 2; ++mi) {
                uint32_t adr = st + a_off + mi * (16 * ROWB) + kb;
                ldsm_x4(adr,         ah[mi][0], ah[mi][1], ah[mi][2], ah[mi][3]);
                ldsm_x4(adr + ARRSZ, al[mi][0], al[mi][1], al[mi][2], al[mi][3]);
            }
            uint32_t bh[8][2];
#pragma unroll
            for (int nb = 0; nb < 4; ++nb) {
                uint32_t adr = st + 2 * ARRSZ + b_off + nb * (16 * ROWB) + kb;
                uint32_t t0, t1, t2, t3;
                ldsm_x4(adr, t0, t1, t2, t3);
                bh[nb*2][0] = t0; bh[nb*2][1] = t1; bh[nb*2+1][0] = t2; bh[nb*2+1][1] = t3;
            }
#pragma unroll
            for (int mi = 0; mi < 2; ++mi)
#pragma unroll
                for (int ni = 0; ni < 8; ++ni) {
                    mma16816(acc[mi][ni], ah[mi], bh[ni]);
                    mma16816(acc[mi][ni], al[mi], bh[ni]);
                }
        }
        __syncthreads();
    }

    const int crow = lane >> 2;
    const int ccol = (lane & 3) * 2;
#pragma unroll
    for (int mi = 0; mi < 2; ++mi) {
#pragma unroll
        for (int half = 0; half < 2; ++half) {
            const int m = m0 + warp_m * 32 + mi * 16 + crow + half * 8;
            const int b = m >> 11, s = m & 2047;
#pragma unroll
            for (int ni = 0; ni < 8; ++ni) {
                const int n = n0 + warp_n * 64 + ni * 8 + ccol;
                float v0 = acc[mi][ni][half * 2 + 0] + bias[n];
                float v1 = acc[mi][ni][half * 2 + 1] + bias[n + 1];
                if (MODE == 1) {
                    v0 *= scale; v1 *= scale;
                    const int head = n >> 6, d = n & 63;
                    const int idx = ((b * NH + head) * NS + s) * NDH + d;
                    __half h0 = __float2half_rn(v0);
                    __half h1 = __float2half_rn(v1);
                    *(uint32_t*)&outH[idx] =
                        pack_h2(__half2float(h0), __half2float(h1));
                    if (outL) {
                        *(uint32_t*)&outL[idx] =
                            pack_h2(v0 - __half2float(h0), v1 - __half2float(h1));
                    }
                } else {
                    *(float2*)&outF[m * ND + n] = make_float2(v0, v1);
                }
            }
        }
    }
}

// ---------------------------------------------------------------------------
// HMMA flash attention (fp16, 2-product). CTA = 128 q rows x one (b,h),
// 8 warps x 16 rows, KV tile 64 double-buffered, 2 CTAs/SM target.
// q hi/lo (A-side), k/v hi only. q pre-scaled by 0.125*log2(e);
// softmax in log2 domain.
// ---------------------------------------------------------------------------
#define QROWB 144
#define QARR  18432            // 128 rows x 144B
#define KARRA 9216             // 64 rows x 144B
#define KVSTG (2 * KARRA)      // Kh + Vh per stage
#define ATTN_SMEM (2 * QARR + 2 * KVSTG)   // 73728

__global__ __launch_bounds__(256, 2) void attn_hmma(
    const __half* __restrict__ qh, const __half* __restrict__ ql,
    const __half* __restrict__ kh, const __half* __restrict__ vh,
    __half* __restrict__ ch, __half* __restrict__ cl,
    const void* __restrict__ masked_raw)
{
    extern __shared__ char smem[];
    const uint32_t sb = smem_u32(smem);
    const int tid  = threadIdx.x;
    const int lane = tid & 31;
    const int wid  = tid >> 5;
    const int bh   = blockIdx.y;
    const int b    = bh >> 3;
    const int h    = bh & 7;
    const int q0   = blockIdx.x << 7;
    const int gbase = bh * NS * NDH;

    int len;
    {
        const long long* ml = (const long long*)masked_raw;
        long long probe = ml[0];
        if (probe >= 1 && probe <= NS) len = (int)ml[b];
        else                           len = ((const int*)masked_raw)[b];
    }
    const int ntiles = (len + 63) >> 6;

    // Load Q hi/lo into smem
#pragma unroll
    for (int i = 0; i < 4; ++i) {
        int c = tid + i * 256;
        int r = c >> 3, blk = c & 7;
        const int src = gbase + (q0 + r) * NDH + blk * 8;
        *(uint4*)(smem + r * QROWB + blk * 16)        = *(const uint4*)(qh + src);
        *(uint4*)(smem + QARR + r * QROWB + blk * 16) = *(const uint4*)(ql + src);
    }

    auto load_kv = [&](int t, int stg) {
        const uint32_t s0 = sb + 2 * QARR + stg * KVSTG;
        const int gk = gbase + (t << 6) * NDH;
#pragma unroll
        for (int i = 0; i < 2; ++i) {
            int c = tid + i * 256;            // 0..511
            int r = c >> 3, blk = c & 7;
            const uint32_t dst = s0 + r * QROWB + blk * 16;
            const int src = gk + r * NDH + blk * 8;
            cp_async16(dst,         kh + src);
            cp_async16(dst + KARRA, vh + src);
        }
        cp_commit();
    };

    load_kv(0, 0);
    __syncthreads();   // Q smem ready

    uint32_t qfh[4][4], qfl[4][4];
    {
        const uint32_t qa = sb + (wid * 16 + (lane & 15)) * QROWB + (lane >> 4) * 16;
#pragma unroll
        for (int ks = 0; ks < 4; ++ks) {
            ldsm_x4(qa + ks * 32,        qfh[ks][0], qfh[ks][1], qfh[ks][2], qfh[ks][3]);
            ldsm_x4(qa + ks * 32 + QARR, qfl[ks][0], qfl[ks][1], qfl[ks][2], qfl[ks][3]);
        }
    }

    float m0r = -1e30f, m1r = -1e30f, lsum0 = 0.0f, lsum1 = 0.0f;
    float o[8][4];
#pragma unroll
    for (int di = 0; di < 8; ++di)
#pragma unroll
        for (int q = 0; q < 4; ++q) o[di][q] = 0.0f;

    for (int t = 0; t < ntiles; ++t) {
        const int stg = t & 1;
        if (t + 1 < ntiles) {
            load_kv(t + 1, stg ^ 1);
            asm volatile("cp.async.wait_group 1;" ::: "memory");
        } else {
            asm volatile("cp.async.wait_group 0;" ::: "memory");
        }
        __syncthreads();

        const uint32_t kbase = sb + 2 * QARR + stg * KVSTG;

        // ---- S = Q K^T  (per-warp 16 x 64) ----
        float s[8][4];
#pragma unroll
        for (int ni = 0; ni < 8; ++ni)
#pragma unroll
            for (int q = 0; q < 4; ++q) s[ni][q] = 0.0f;

#pragma unroll
        for (int ks = 0; ks < 4; ++ks) {
#pragma unroll
            for (int nb = 0; nb < 4; ++nb) {
                const uint32_t adr = kbase
                    + (nb * 16 + (lane & 7) + 8 * (lane >> 4)) * QROWB
                    + ((lane >> 3) & 1) * 16 + ks * 32;
                uint32_t t0, t1, t2, t3;
                ldsm_x4(adr, t0, t1, t2, t3);
                uint32_t bh0[2] = {t0, t1}, bh1[2] = {t2, t3};
                mma16816(s[nb*2],   qfh[ks], bh0);
                mma16816(s[nb*2],   qfl[ks], bh0);
                mma16816(s[nb*2+1], qfh[ks], bh1);
                mma16816(s[nb*2+1], qfl[ks], bh1);
            }
        }

        // ---- mask + online softmax (log2 domain) ----
        const int kv0 = t << 6;
        const int cb  = kv0 + 2 * (lane & 3);
        float tmax0 = -1e30f, tmax1 = -1e30f;
#pragma unroll
        for (int ni = 0; ni < 8; ++ni) {
            const int c0 = cb + 8 * ni;
            if (c0     >= len) { s[ni][0] = -1e30f; s[ni][2] = -1e30f; }
            if (c0 + 1 >= len) { s[ni][1] = -1e30f; s[ni][3] = -1e30f; }
            tmax0 = fmaxf(tmax0, fmaxf(s[ni][0], s[ni][1]));
            tmax1 = fmaxf(tmax1, fmaxf(s[ni][2], s[ni][3]));
        }
        tmax0 = fmaxf(tmax0, __shfl_xor_sync(0xffffffffu, tmax0, 1));
        tmax0 = fmaxf(tmax0, __shfl_xor_sync(0xffffffffu, tmax0, 2));
        tmax1 = fmaxf(tmax1, __shfl_xor_sync(0xffffffffu, tmax1, 1));
        tmax1 = fmaxf(tmax1, __shfl_xor_sync(0xffffffffu, tmax1, 2));

        const float mn0 = fmaxf(m0r, tmax0);
        const float mn1 = fmaxf(m1r, tmax1);
        const float sc0 = ex2(m0r - mn0);
        const float sc1 = ex2(m1r - mn1);
        m0r = mn0; m1r = mn1;

        float ps0 = 0.0f, ps1 = 0.0f;
#pragma unroll
        for (int ni = 0; ni < 8; ++ni) {
            float p0 = ex2(s[ni][0] - mn0);
            float p1 = ex2(s[ni][1] - mn0);
            float p2 = ex2(s[ni][2] - mn1);
            float p3 = ex2(s[ni][3] - mn1);
            ps0 += p0 + p1;
            ps1 += p2 + p3;
            __half h0 = __float2half_rn(p0);
            __half h1 = __float2half_rn(p1);
            __half h2 = __float2half_rn(p2);
            __half h3 = __float2half_rn(p3);
            s[ni][0] = __uint_as_float(pack_h2(__half2float(h0), __half2float(h1)));
            s[ni][1] = __uint_as_float(pack_h2(p0 - __half2float(h0),
                                               p1 - __half2float(h1)));
            s[ni][2] = __uint_as_float(pack_h2(__half2float(h2), __half2float(h3)));
            s[ni][3] = __uint_as_float(pack_h2(p2 - __half2float(h2),
                                               p3 - __half2float(h3)));
        }
        ps0 += __shfl_xor_sync(0xffffffffu, ps0, 1);
        ps0 += __shfl_xor_sync(0xffffffffu, ps0, 2);
        ps1 += __shfl_xor_sync(0xffffffffu, ps1, 1);
        ps1 += __shfl_xor_sync(0xffffffffu, ps1, 2);
        lsum0 = lsum0 * sc0 + ps0;
        lsum1 = lsum1 * sc1 + ps1;
#pragma unroll
        for (int di = 0; di < 8; ++di) {
            o[di][0] *= sc0; o[di][1] *= sc0;
            o[di][2] *= sc1; o[di][3] *= sc1;
        }

        // ---- O += P V  (V hi only) ----
        const uint32_t vbase = kbase + KARRA;
#pragma unroll
        for (int ks2 = 0; ks2 < 4; ++ks2) {
            uint32_t Ahf[4] = {
                __float_as_uint(s[2*ks2][0]),   __float_as_uint(s[2*ks2][2]),
                __float_as_uint(s[2*ks2+1][0]), __float_as_uint(s[2*ks2+1][2]) };
            uint32_t Alf[4] = {
                __float_as_uint(s[2*ks2][1]),   __float_as_uint(s[2*ks2][3]),
                __float_as_uint(s[2*ks2+1][1]), __float_as_uint(s[2*ks2+1][3]) };
#pragma unroll
            for (int db = 0; db < 4; ++db) {
                const uint32_t adr = vbase
                    + (ks2 * 16 + (lane & 7) + 8 * ((lane >> 3) & 1)) * QROWB
                    + ((lane >> 4) & 1) * 16 + db * 32;
                uint32_t t0, t1, t2, t3;
                ldsm_x4_t(adr, t0, t1, t2, t3);
                uint32_t vh0[2] = {t0, t1}, vh1[2] = {t2, t3};
                mma16816(o[db*2],   Ahf, vh0);
                mma16816(o[db*2],   Alf, vh0);
                mma16816(o[db*2+1], Ahf, vh1);
                mma16816(o[db*2+1], Alf, vh1);
            }
        }
        __syncthreads();
    }

    // ---- normalize + write ctx fp16 hi/lo [B,S,D] ----
    const float inv0 = 1.0f / lsum0;
    const float inv1 = 1.0f / lsum1;
    const int r  = lane >> 2;
    const int dc = 2 * (lane & 3);
    const int qrow0 = q0 + wid * 16 + r;
#pragma unroll
    for (int di = 0; di < 8; ++di) {
        const int d = 8 * di + dc;
        {
            const int idx = ((b * NS + qrow0) * ND) + h * NDH + d;
            float v0 = o[di][0] * inv0, v1 = o[di][1] * inv0;
            __half h0 = __float2half_rn(v0);
            __half h1 = __float2half_rn(v1);
            *(uint32_t*)&ch[idx] = pack_h2(__half2float(h0), __half2float(h1));
            *(uint32_t*)&cl[idx] = pack_h2(v0 - __half2float(h0), v1 - __half2float(h1));
        }
        {
            const int idx = ((b * NS + qrow0 + 8) * ND) + h * NDH + d;
            float v0 = o[di][2] * inv1, v1 = o[di][3] * inv1;
            __half h0 = __float2half_rn(v0);
            __half h1 = __float2half_rn(v1);
            *(uint32_t*)&ch[idx] = pack_h2(__half2float(h0), __half2float(h1));
            *(uint32_t*)&cl[idx] = pack_h2(v0 - __half2float(h0), v1 - __half2float(h1));
        }
    }
}

// ---------------------------------------------------------------------------
extern "C" void kernel_launch(void* const* d_in, const int* in_sizes, int n_in,
                              void* d_out, int out_size)
{
    (void)in_sizes; (void)n_in; (void)out_size;
    const float* Q  = (const float*)d_in[0];
    const float* K  = (const float*)d_in[1];
    const float* V  = (const float*)d_in[2];
    const float* Wq = (const float*)d_in[3];
    const float* bq = (const float*)d_in[4];
    const float* Wk = (const float*)d_in[5];
    const float* bk = (const float*)d_in[6];
    const float* Wv = (const float*)d_in[7];
    const float* bv = (const float*)d_in[8];
    const float* Wo = (const float*)d_in[9];
    const float* bo = (const float*)d_in[10];
    const void*  mk = d_in[11];
    float* out = (float*)d_out;

    __half *pqh, *pql, *pkh, *pvh, *pch, *pcl, *pah, *pal, *pwh;
    cudaGetSymbolAddress((void**)&pqh, g_qh);
    cudaGetSymbolAddress((void**)&pql, g_ql);
    cudaGetSymbolAddress((void**)&pkh, g_kh);
    cudaGetSymbolAddress((void**)&pvh, g_vh);
    cudaGetSymbolAddress((void**)&pch, g_ch);
    cudaGetSymbolAddress((void**)&pcl, g_cl);
    cudaGetSymbolAddress((void**)&pah, g_ah);
    cudaGetSymbolAddress((void**)&pal, g_al);
    cudaGetSymbolAddress((void**)&pwh, g_wh);

    const int nx4 = (NB * NS * ND) / 4;
    const int nw4 = (ND * ND) / 4;

    cudaFuncSetAttribute(proj_hmma<1>, cudaFuncAttributeMaxDynamicSharedMemorySize, PROJ_SMEM);
    cudaFuncSetAttribute(proj_hmma<0>, cudaFuncAttributeMaxDynamicSharedMemorySize, PROJ_SMEM);
    cudaFuncSetAttribute(attn_hmma, cudaFuncAttributeMaxDynamicSharedMemorySize, ATTN_SMEM);

    dim3 gp(64, 4);
    const float QSCALE = 0.125f * 1.4426950408889634f;  // 1/sqrt(64) * log2(e)

    // Q projection
    conv_h <<<(nw4 + 255) / 256, 256>>>(Wq, pwh, nw4);
    conv_hl<<<(nx4 + 255) / 256, 256>>>(Q, pah, pal, nx4);
    proj_hmma<1><<<gp, 256, PROJ_SMEM>>>(pah, pal, pwh, bq, nullptr, pqh, pql, QSCALE);
    // K projection (hi only)
    conv_h <<<(nw4 + 255) / 256, 256>>>(Wk, pwh, nw4);
    conv_hl<<<(nx4 + 255) / 256, 256>>>(K, pah, pal, nx4);
    proj_hmma<1><<<gp, 256, PROJ_SMEM>>>(pah, pal, pwh, bk, nullptr, pkh, nullptr, 1.0f);
    // V projection (hi only)
    conv_h <<<(nw4 + 255) / 256, 256>>>(Wv, pwh, nw4);
    conv_hl<<<(nx4 + 255) / 256, 256>>>(V, pah, pal, nx4);
    proj_hmma<1><<<gp, 256, PROJ_SMEM>>>(pah, pal, pwh, bv, nullptr, pvh, nullptr, 1.0f);

    // Attention
    attn_hmma<<<dim3(NS / 128, NB * NH), 256, ATTN_SMEM>>>(
        pqh, pql, pkh, pvh, pch, pcl, mk);

    // Output projection
    conv_h<<<(nw4 + 255) / 256, 256>>>(Wo, pwh, nw4);
    proj_hmma<0><<<gp, 256, PROJ_SMEM>>>(pch, pcl, pwh, bo, out, nullptr, nullptr, 1.0f);
}

// round 9
// speedup vs baseline: 1.7796x; 1.1673x over previous
#include <cuda_runtime.h>
#include <cuda_fp16.h>
#include <cstdint>

#define NB  4
#define NS  2048
#define ND  512
#define NH  8
#define NDH 64

// ---------------------------------------------------------------------------
// Scratch (device globals: allocation-free rule)
// ---------------------------------------------------------------------------
__device__ __half g_qh[NB * NH * NS * NDH];
__device__ __half g_ql[NB * NH * NS * NDH];
__device__ __half g_kh[NB * NH * NS * NDH];   // hi only
__device__ __half g_vh[NB * NH * NS * NDH];   // hi only
__device__ __half g_ch[NB * NS * ND];         // ctx hi only
__device__ __half g_ah[3][NB * NS * ND];      // Q/K/V activation hi
__device__ __half g_al[3][NB * NS * ND];      // Q/K/V activation lo
__device__ __half g_wh[4][ND * ND];           // Wq,Wk,Wv,Wo hi

// ---------------------------------------------------------------------------
__device__ __forceinline__ uint32_t smem_u32(const void* p) {
    uint32_t a;
    asm("{ .reg .u64 t; cvta.to.shared.u64 t, %1; cvt.u32.u64 %0, t; }"
        : "=r"(a) : "l"(p));
    return a;
}
__device__ __forceinline__ void cp_async16(uint32_t dst, const void* src) {
    asm volatile("cp.async.ca.shared.global [%0], [%1], 16;"
                 :: "r"(dst), "l"(src) : "memory");
}
__device__ __forceinline__ void cp_commit() {
    asm volatile("cp.async.commit_group;" ::: "memory");
}
__device__ __forceinline__ void ldsm_x4(uint32_t addr, uint32_t& r0, uint32_t& r1,
                                        uint32_t& r2, uint32_t& r3) {
    asm volatile("ldmatrix.sync.aligned.m8n8.x4.shared.b16 {%0,%1,%2,%3}, [%4];"
                 : "=r"(r0), "=r"(r1), "=r"(r2), "=r"(r3) : "r"(addr));
}
__device__ __forceinline__ void ldsm_x4_t(uint32_t addr, uint32_t& r0, uint32_t& r1,
                                          uint32_t& r2, uint32_t& r3) {
    asm volatile("ldmatrix.sync.aligned.m8n8.x4.trans.shared.b16 {%0,%1,%2,%3}, [%4];"
                 : "=r"(r0), "=r"(r1), "=r"(r2), "=r"(r3) : "r"(addr));
}
__device__ __forceinline__ void mma16816(float* c, const uint32_t* a, const uint32_t* b) {
    asm volatile(
        "mma.sync.aligned.m16n8k16.row.col.f32.f16.f16.f32 "
        "{%0,%1,%2,%3}, {%4,%5,%6,%7}, {%8,%9}, {%0,%1,%2,%3};"
        : "+f"(c[0]), "+f"(c[1]), "+f"(c[2]), "+f"(c[3])
        : "r"(a[0]), "r"(a[1]), "r"(a[2]), "r"(a[3]), "r"(b[0]), "r"(b[1]));
}
__device__ __forceinline__ float ex2(float x) {
    float y;
    asm("ex2.approx.ftz.f32 %0, %1;" : "=f"(y) : "f"(x));
    return y;
}
__device__ __forceinline__ uint32_t pack_h2(float a, float b) {
    __half2 t = __floats2half2_rn(a, b);
    return *(uint32_t*)&t;
}

// ---------------------------------------------------------------------------
// Merged conversions (scalar pointer args; switch on blockIdx.y)
// ---------------------------------------------------------------------------
__global__ __launch_bounds__(256) void conv_w4(
    const float* w0, const float* w1, const float* w2, const float* w3,
    __half* h0, __half* h1, __half* h2, __half* h3, int n4)
{
    const float* in; __half* hi;
    switch (blockIdx.y) {
        case 0:  in = w0; hi = h0; break;
        case 1:  in = w1; hi = h1; break;
        case 2:  in = w2; hi = h2; break;
        default: in = w3; hi = h3; break;
    }
    int idx = blockIdx.x * 256 + threadIdx.x;
    if (idx >= n4) return;
    float4 v = ((const float4*)in)[idx];
    __half h[4] = {__float2half_rn(v.x), __float2half_rn(v.y),
                   __float2half_rn(v.z), __float2half_rn(v.w)};
    ((uint2*)hi)[idx] = *(uint2*)h;
}

__global__ __launch_bounds__(256) void conv_a3(
    const float* a0, const float* a1, const float* a2,
    __half* h0, __half* l0, __half* h1, __half* l1,
    __half* h2, __half* l2, int n4)
{
    const float* in; __half *hi, *lo;
    switch (blockIdx.y) {
        case 0:  in = a0; hi = h0; lo = l0; break;
        case 1:  in = a1; hi = h1; lo = l1; break;
        default: in = a2; hi = h2; lo = l2; break;
    }
    int idx = blockIdx.x * 256 + threadIdx.x;
    if (idx >= n4) return;
    float4 v = ((const float4*)in)[idx];
    float f[4] = {v.x, v.y, v.z, v.w};
    __half h[4], l[4];
#pragma unroll
    for (int i = 0; i < 4; ++i) {
        h[i] = __float2half_rn(f[i]);
        l[i] = __float2half_rn(f[i] - __half2float(h[i]));
    }
    ((uint2*)hi)[idx] = *(uint2*)h;
    ((uint2*)lo)[idx] = *(uint2*)l;
}

// ---------------------------------------------------------------------------
// HMMA projection GEMM: C[8192,512] = X @ W^T + bias
// APROD = A-side products (2 = hi/lo, 1 = hi only). B hi-only. 2 CTAs/SM.
// MODE 0: fp32 row-major out. MODE 1: fp16 hi(/lo) out, head layout, scaled.
// ---------------------------------------------------------------------------
#define ROWB   80
#define ARRSZ  10240

template <int MODE, int APROD>
__global__ __launch_bounds__(256, 2) void proj_hmma(
    const __half* __restrict__ Ah, const __half* __restrict__ Al,
    const __half* __restrict__ Bh,
    const float* __restrict__ bias, float* __restrict__ outF,
    __half* __restrict__ outH, __half* __restrict__ outL, float scale)
{
    constexpr int NARR = APROD + 1;
    constexpr int STG  = NARR * ARRSZ;

    extern __shared__ char smem[];
    const uint32_t sb = smem_u32(smem);
    const int tid  = threadIdx.x;
    const int lane = tid & 31;
    const int wid  = tid >> 5;
    const int warp_m = wid & 3;
    const int warp_n = wid >> 2;
    const int m0 = blockIdx.x * 128;
    const int n0 = blockIdx.y * 128;

    const int r0c = (tid + 0)   >> 2, s0c = tid & 3;
    const int r1c = (tid + 256) >> 2, s1c = tid & 3;

    const uint32_t a_off = (uint32_t)((warp_m * 32 + (lane & 15)) * ROWB + (lane >> 4) * 16);
    const uint32_t b_off = (uint32_t)((warp_n * 64 + (lane & 7) + 8 * (lane >> 4)) * ROWB
                                      + ((lane >> 3) & 1) * 16);

    float acc[2][8][4];
#pragma unroll
    for (int mi = 0; mi < 2; ++mi)
#pragma unroll
        for (int ni = 0; ni < 8; ++ni)
#pragma unroll
            for (int q = 0; q < 4; ++q) acc[mi][ni][q] = 0.0f;

    auto load_chunk = [&](int c, int stage) {
        const int k0 = c * 32;
        const uint32_t st = sb + stage * STG;
#pragma unroll
        for (int arr = 0; arr < NARR; ++arr) {
            const __half* base = (arr == NARR - 1) ? Bh : (arr == 0 ? Ah : Al);
            const int rbase = (arr == NARR - 1) ? n0 : m0;
            cp_async16(st + arr * ARRSZ + r0c * ROWB + s0c * 16,
                       base + (rbase + r0c) * ND + k0 + s0c * 8);
            cp_async16(st + arr * ARRSZ + r1c * ROWB + s1c * 16,
                       base + (rbase + r1c) * ND + k0 + s1c * 8);
        }
        cp_commit();
    };

    load_chunk(0, 0);

    for (int c = 0; c < 16; ++c) {
        const int stage = c & 1;
        if (c < 15) {
            load_chunk(c + 1, stage ^ 1);
            asm volatile("cp.async.wait_group 1;" ::: "memory");
        } else {
            asm volatile("cp.async.wait_group 0;" ::: "memory");
        }
        __syncthreads();

        const uint32_t st = sb + stage * STG;
#pragma unroll
        for (int ks = 0; ks < 2; ++ks) {
            const uint32_t kb = ks * 32;
            uint32_t ah[2][4], al[2][4];
#pragma unroll
            for (int mi = 0; mi < 2; ++mi) {
                uint32_t adr = st + a_off + mi * (16 * ROWB) + kb;
                ldsm_x4(adr, ah[mi][0], ah[mi][1], ah[mi][2], ah[mi][3]);
                if (APROD == 2)
                    ldsm_x4(adr + ARRSZ, al[mi][0], al[mi][1], al[mi][2], al[mi][3]);
            }
            uint32_t bh[8][2];
#pragma unroll
            for (int nb = 0; nb < 4; ++nb) {
                uint32_t adr = st + (NARR - 1) * ARRSZ + b_off + nb * (16 * ROWB) + kb;
                uint32_t t0, t1, t2, t3;
                ldsm_x4(adr, t0, t1, t2, t3);
                bh[nb*2][0] = t0; bh[nb*2][1] = t1; bh[nb*2+1][0] = t2; bh[nb*2+1][1] = t3;
            }
#pragma unroll
            for (int mi = 0; mi < 2; ++mi)
#pragma unroll
                for (int ni = 0; ni < 8; ++ni) {
                    mma16816(acc[mi][ni], ah[mi], bh[ni]);
                    if (APROD == 2) mma16816(acc[mi][ni], al[mi], bh[ni]);
                }
        }
        __syncthreads();
    }

    const int crow = lane >> 2;
    const int ccol = (lane & 3) * 2;
#pragma unroll
    for (int mi = 0; mi < 2; ++mi) {
#pragma unroll
        for (int half = 0; half < 2; ++half) {
            const int m = m0 + warp_m * 32 + mi * 16 + crow + half * 8;
            const int b = m >> 11, s = m & 2047;
#pragma unroll
            for (int ni = 0; ni < 8; ++ni) {
                const int n = n0 + warp_n * 64 + ni * 8 + ccol;
                float v0 = acc[mi][ni][half * 2 + 0] + bias[n];
                float v1 = acc[mi][ni][half * 2 + 1] + bias[n + 1];
                if (MODE == 1) {
                    v0 *= scale; v1 *= scale;
                    const int head = n >> 6, d = n & 63;
                    const int idx = ((b * NH + head) * NS + s) * NDH + d;
                    __half h0 = __float2half_rn(v0);
                    __half h1 = __float2half_rn(v1);
                    *(uint32_t*)&outH[idx] =
                        pack_h2(__half2float(h0), __half2float(h1));
                    if (outL) {
                        *(uint32_t*)&outL[idx] =
                            pack_h2(v0 - __half2float(h0), v1 - __half2float(h1));
                    }
                } else {
                    *(float2*)&outF[m * ND + n] = make_float2(v0, v1);
                }
            }
        }
    }
}

#define PROJ_SMEM_2 (2 * 3 * ARRSZ)   // APROD=2: 61440
#define PROJ_SMEM_1 (2 * 2 * ARRSZ)   // APROD=1: 40960

// ---------------------------------------------------------------------------
// HMMA flash attention (fp16). CTA = 128 q rows x one (b,h), 8 warps,
// KV tile 64 double-buffered, 2 CTAs/SM. q hi/lo, k/v hi, P hi only.
// q pre-scaled by 0.125*log2(e); softmax in log2 domain. ctx hi only.
// ---------------------------------------------------------------------------
#define QROWB 144
#define QARR  18432            // 128 rows x 144B
#define KARRA 9216             // 64 rows x 144B
#define KVSTG (2 * KARRA)
#define ATTN_SMEM (2 * QARR + 2 * KVSTG)   // 73728

__global__ __launch_bounds__(256, 2) void attn_hmma(
    const __half* __restrict__ qh, const __half* __restrict__ ql,
    const __half* __restrict__ kh, const __half* __restrict__ vh,
    __half* __restrict__ ch,
    const void* __restrict__ masked_raw)
{
    extern __shared__ char smem[];
    const uint32_t sb = smem_u32(smem);
    const int tid  = threadIdx.x;
    const int lane = tid & 31;
    const int wid  = tid >> 5;
    const int bh   = blockIdx.y;
    const int b    = bh >> 3;
    const int h    = bh & 7;
    const int q0   = blockIdx.x << 7;
    const int gbase = bh * NS * NDH;

    int len;
    {
        const long long* ml = (const long long*)masked_raw;
        long long probe = ml[0];
        if (probe >= 1 && probe <= NS) len = (int)ml[b];
        else                           len = ((const int*)masked_raw)[b];
    }
    const int ntiles = (len + 63) >> 6;

    // Load Q hi/lo into smem
#pragma unroll
    for (int i = 0; i < 4; ++i) {
        int c = tid + i * 256;
        int r = c >> 3, blk = c & 7;
        const int src = gbase + (q0 + r) * NDH + blk * 8;
        *(uint4*)(smem + r * QROWB + blk * 16)        = *(const uint4*)(qh + src);
        *(uint4*)(smem + QARR + r * QROWB + blk * 16) = *(const uint4*)(ql + src);
    }

    auto load_kv = [&](int t, int stg) {
        const uint32_t s0 = sb + 2 * QARR + stg * KVSTG;
        const int gk = gbase + (t << 6) * NDH;
#pragma unroll
        for (int i = 0; i < 2; ++i) {
            int c = tid + i * 256;
            int r = c >> 3, blk = c & 7;
            const uint32_t dst = s0 + r * QROWB + blk * 16;
            const int src = gk + r * NDH + blk * 8;
            cp_async16(dst,         kh + src);
            cp_async16(dst + KARRA, vh + src);
        }
        cp_commit();
    };

    load_kv(0, 0);
    __syncthreads();

    uint32_t qfh[4][4], qfl[4][4];
    {
        const uint32_t qa = sb + (wid * 16 + (lane & 15)) * QROWB + (lane >> 4) * 16;
#pragma unroll
        for (int ks = 0; ks < 4; ++ks) {
            ldsm_x4(qa + ks * 32,        qfh[ks][0], qfh[ks][1], qfh[ks][2], qfh[ks][3]);
            ldsm_x4(qa + ks * 32 + QARR, qfl[ks][0], qfl[ks][1], qfl[ks][2], qfl[ks][3]);
        }
    }

    float m0r = -1e30f, m1r = -1e30f, lsum0 = 0.0f, lsum1 = 0.0f;
    float o[8][4];
#pragma unroll
    for (int di = 0; di < 8; ++di)
#pragma unroll
        for (int q = 0; q < 4; ++q) o[di][q] = 0.0f;

    for (int t = 0; t < ntiles; ++t) {
        const int stg = t & 1;
        if (t + 1 < ntiles) {
            load_kv(t + 1, stg ^ 1);
            asm volatile("cp.async.wait_group 1;" ::: "memory");
        } else {
            asm volatile("cp.async.wait_group 0;" ::: "memory");
        }
        __syncthreads();

        const uint32_t kbase = sb + 2 * QARR + stg * KVSTG;

        // ---- S = Q K^T  (per-warp 16 x 64) ----
        float s[8][4];
#pragma unroll
        for (int ni = 0; ni < 8; ++ni)
#pragma unroll
            for (int q = 0; q < 4; ++q) s[ni][q] = 0.0f;

#pragma unroll
        for (int ks = 0; ks < 4; ++ks) {
#pragma unroll
            for (int nb = 0; nb < 4; ++nb) {
                const uint32_t adr = kbase
                    + (nb * 16 + (lane & 7) + 8 * (lane >> 4)) * QROWB
                    + ((lane >> 3) & 1) * 16 + ks * 32;
                uint32_t t0, t1, t2, t3;
                ldsm_x4(adr, t0, t1, t2, t3);
                uint32_t bh0[2] = {t0, t1}, bh1[2] = {t2, t3};
                mma16816(s[nb*2],   qfh[ks], bh0);
                mma16816(s[nb*2],   qfl[ks], bh0);
                mma16816(s[nb*2+1], qfh[ks], bh1);
                mma16816(s[nb*2+1], qfl[ks], bh1);
            }
        }

        // ---- mask + online softmax (log2 domain) ----
        const int kv0 = t << 6;
        const int cb  = kv0 + 2 * (lane & 3);
        float tmax0 = -1e30f, tmax1 = -1e30f;
#pragma unroll
        for (int ni = 0; ni < 8; ++ni) {
            const int c0 = cb + 8 * ni;
            if (c0     >= len) { s[ni][0] = -1e30f; s[ni][2] = -1e30f; }
            if (c0 + 1 >= len) { s[ni][1] = -1e30f; s[ni][3] = -1e30f; }
            tmax0 = fmaxf(tmax0, fmaxf(s[ni][0], s[ni][1]));
            tmax1 = fmaxf(tmax1, fmaxf(s[ni][2], s[ni][3]));
        }
        tmax0 = fmaxf(tmax0, __shfl_xor_sync(0xffffffffu, tmax0, 1));
        tmax0 = fmaxf(tmax0, __shfl_xor_sync(0xffffffffu, tmax0, 2));
        tmax1 = fmaxf(tmax1, __shfl_xor_sync(0xffffffffu, tmax1, 1));
        tmax1 = fmaxf(tmax1, __shfl_xor_sync(0xffffffffu, tmax1, 2));

        const float mn0 = fmaxf(m0r, tmax0);
        const float mn1 = fmaxf(m1r, tmax1);
        const float sc0 = ex2(m0r - mn0);
        const float sc1 = ex2(m1r - mn1);
        m0r = mn0; m1r = mn1;

        float ps0 = 0.0f, ps1 = 0.0f;
        // P packed hi-only: s[ni][0] = h2(p rowA), s[ni][2] = h2(p rowB)
#pragma unroll
        for (int ni = 0; ni < 8; ++ni) {
            float p0 = ex2(s[ni][0] - mn0);
            float p1 = ex2(s[ni][1] - mn0);
            float p2 = ex2(s[ni][2] - mn1);
            float p3 = ex2(s[ni][3] - mn1);
            ps0 += p0 + p1;
            ps1 += p2 + p3;
            s[ni][0] = __uint_as_float(pack_h2(p0, p1));
            s[ni][2] = __uint_as_float(pack_h2(p2, p3));
        }
        ps0 += __shfl_xor_sync(0xffffffffu, ps0, 1);
        ps0 += __shfl_xor_sync(0xffffffffu, ps0, 2);
        ps1 += __shfl_xor_sync(0xffffffffu, ps1, 1);
        ps1 += __shfl_xor_sync(0xffffffffu, ps1, 2);
        lsum0 = lsum0 * sc0 + ps0;
        lsum1 = lsum1 * sc1 + ps1;
#pragma unroll
        for (int di = 0; di < 8; ++di) {
            o[di][0] *= sc0; o[di][1] *= sc0;
            o[di][2] *= sc1; o[di][3] *= sc1;
        }

        // ---- O += P V  (P hi only, V hi only) ----
        const uint32_t vbase = kbase + KARRA;
#pragma unroll
        for (int ks2 = 0; ks2 < 4; ++ks2) {
            uint32_t Ahf[4] = {
                __float_as_uint(s[2*ks2][0]),   __float_as_uint(s[2*ks2][2]),
                __float_as_uint(s[2*ks2+1][0]), __float_as_uint(s[2*ks2+1][2]) };
#pragma unroll
            for (int db = 0; db < 4; ++db) {
                const uint32_t adr = vbase
                    + (ks2 * 16 + (lane & 7) + 8 * ((lane >> 3) & 1)) * QROWB
                    + ((lane >> 4) & 1) * 16 + db * 32;
                uint32_t t0, t1, t2, t3;
                ldsm_x4_t(adr, t0, t1, t2, t3);
                uint32_t vh0[2] = {t0, t1}, vh1[2] = {t2, t3};
                mma16816(o[db*2],   Ahf, vh0);
                mma16816(o[db*2+1], Ahf, vh1);
            }
        }
        __syncthreads();
    }

    // ---- normalize + write ctx hi-only [B,S,D] ----
    const float inv0 = 1.0f / lsum0;
    const float inv1 = 1.0f / lsum1;
    const int r  = lane >> 2;
    const int dc = 2 * (lane & 3);
    const int qrow0 = q0 + wid * 16 + r;
#pragma unroll
    for (int di = 0; di < 8; ++di) {
        const int d = 8 * di + dc;
        *(uint32_t*)&ch[((b * NS + qrow0) * ND) + h * NDH + d] =
            pack_h2(o[di][0] * inv0, o[di][1] * inv0);
        *(uint32_t*)&ch[((b * NS + qrow0 + 8) * ND) + h * NDH + d] =
            pack_h2(o[di][2] * inv1, o[di][3] * inv1);
    }
}

// ---------------------------------------------------------------------------
extern "C" void kernel_launch(void* const* d_in, const int* in_sizes, int n_in,
                              void* d_out, int out_size)
{
    (void)in_sizes; (void)n_in; (void)out_size;
    const float* Q  = (const float*)d_in[0];
    const float* K  = (const float*)d_in[1];
    const float* V  = (const float*)d_in[2];
    const float* Wq = (const float*)d_in[3];
    const float* bq = (const float*)d_in[4];
    const float* Wk = (const float*)d_in[5];
    const float* bk = (const float*)d_in[6];
    const float* Wv = (const float*)d_in[7];
    const float* bv = (const float*)d_in[8];
    const float* Wo = (const float*)d_in[9];
    const float* bo = (const float*)d_in[10];
    const void*  mk = d_in[11];
    float* out = (float*)d_out;

    __half *pqh, *pql, *pkh, *pvh, *pch, *pah, *pal, *pwh;
    cudaGetSymbolAddress((void**)&pqh, g_qh);
    cudaGetSymbolAddress((void**)&pql, g_ql);
    cudaGetSymbolAddress((void**)&pkh, g_kh);
    cudaGetSymbolAddress((void**)&pvh, g_vh);
    cudaGetSymbolAddress((void**)&pch, g_ch);
    cudaGetSymbolAddress((void**)&pah, g_ah);
    cudaGetSymbolAddress((void**)&pal, g_al);
    cudaGetSymbolAddress((void**)&pwh, g_wh);

    const int NACT = NB * NS * ND;   // 4194304
    const int NW   = ND * ND;        // 262144
    const int nx4 = NACT / 4;
    const int nw4 = NW / 4;

    cudaFuncSetAttribute((const void*)proj_hmma<1, 2>,
                         cudaFuncAttributeMaxDynamicSharedMemorySize, PROJ_SMEM_2);
    cudaFuncSetAttribute((const void*)proj_hmma<0, 1>,
                         cudaFuncAttributeMaxDynamicSharedMemorySize, PROJ_SMEM_1);
    cudaFuncSetAttribute((const void*)attn_hmma,
                         cudaFuncAttributeMaxDynamicSharedMemorySize, ATTN_SMEM);

    dim3 gp(64, 4);
    const float QSCALE = 0.125f * 1.4426950408889634f;  // 1/sqrt(64) * log2(e)

    // 1) all 4 weight hi conversions
    conv_w4<<<dim3((nw4 + 255) / 256, 4), 256>>>(
        Wq, Wk, Wv, Wo, pwh, pwh + NW, pwh + 2 * NW, pwh + 3 * NW, nw4);
    // 2) Q/K/V activation hi/lo conversions
    conv_a3<<<dim3((nx4 + 255) / 256, 3), 256>>>(
        Q, K, V, pah, pal, pah + NACT, pal + NACT, pah + 2 * NACT, pal + 2 * NACT, nx4);
    // 3-5) projections
    proj_hmma<1, 2><<<gp, 256, PROJ_SMEM_2>>>(
        pah, pal, pwh, bq, nullptr, pqh, pql, QSCALE);
    proj_hmma<1, 2><<<gp, 256, PROJ_SMEM_2>>>(
        pah + NACT, pal + NACT, pwh + NW, bk, nullptr, pkh, nullptr, 1.0f);
    proj_hmma<1, 2><<<gp, 256, PROJ_SMEM_2>>>(
        pah + 2 * NACT, pal + 2 * NACT, pwh + 2 * NW, bv, nullptr, pvh, nullptr, 1.0f);
    // 6) attention (ctx hi only)
    attn_hmma<<<dim3(NS / 128, NB * NH), 256, ATTN_SMEM>>>(
        pqh, pql, pkh, pvh, pch, mk);
    // 7) output projection (single product)
    proj_hmma<0, 1><<<gp, 256, PROJ_SMEM_1>>>(
        pch, nullptr, pwh + 3 * NW, bo, out, nullptr, nullptr, 1.0f);
}

// round 10
// speedup vs baseline: 1.9821x; 1.1138x over previous
#include <cuda_runtime.h>
#include <cuda_fp16.h>
#include <cstdint>

#define NB  4
#define NS  2048
#define ND  512
#define NH  8
#define NDH 64

// ---------------------------------------------------------------------------
// Scratch (device globals: allocation-free rule)
// ---------------------------------------------------------------------------
__device__ __half g_qh[NB * NH * NS * NDH];
__device__ __half g_ql[NB * NH * NS * NDH];
__device__ __half g_kh[NB * NH * NS * NDH];   // hi only
__device__ __half g_vh[NB * NH * NS * NDH];   // hi only
__device__ __half g_ch[NB * NS * ND];         // ctx hi only
__device__ __half g_ah[3][NB * NS * ND];      // Q/K/V activation hi
__device__ __half g_al[NB * NS * ND];         // Q activation lo (only Q needs lo)
__device__ __half g_wh[4][ND * ND];           // Wq,Wk,Wv,Wo hi

// ---------------------------------------------------------------------------
__device__ __forceinline__ uint32_t smem_u32(const void* p) {
    uint32_t a;
    asm("{ .reg .u64 t; cvta.to.shared.u64 t, %1; cvt.u32.u64 %0, t; }"
        : "=r"(a) : "l"(p));
    return a;
}
__device__ __forceinline__ void cp_async16(uint32_t dst, const void* src) {
    asm volatile("cp.async.ca.shared.global [%0], [%1], 16;"
                 :: "r"(dst), "l"(src) : "memory");
}
__device__ __forceinline__ void cp_commit() {
    asm volatile("cp.async.commit_group;" ::: "memory");
}
__device__ __forceinline__ void ldsm_x4(uint32_t addr, uint32_t& r0, uint32_t& r1,
                                        uint32_t& r2, uint32_t& r3) {
    asm volatile("ldmatrix.sync.aligned.m8n8.x4.shared.b16 {%0,%1,%2,%3}, [%4];"
                 : "=r"(r0), "=r"(r1), "=r"(r2), "=r"(r3) : "r"(addr));
}
__device__ __forceinline__ void ldsm_x4_t(uint32_t addr, uint32_t& r0, uint32_t& r1,
                                          uint32_t& r2, uint32_t& r3) {
    asm volatile("ldmatrix.sync.aligned.m8n8.x4.trans.shared.b16 {%0,%1,%2,%3}, [%4];"
                 : "=r"(r0), "=r"(r1), "=r"(r2), "=r"(r3) : "r"(addr));
}
__device__ __forceinline__ void mma16816(float* c, const uint32_t* a, const uint32_t* b) {
    asm volatile(
        "mma.sync.aligned.m16n8k16.row.col.f32.f16.f16.f32 "
        "{%0,%1,%2,%3}, {%4,%5,%6,%7}, {%8,%9}, {%0,%1,%2,%3};"
        : "+f"(c[0]), "+f"(c[1]), "+f"(c[2]), "+f"(c[3])
        : "r"(a[0]), "r"(a[1]), "r"(a[2]), "r"(a[3]), "r"(b[0]), "r"(b[1]));
}
__device__ __forceinline__ float ex2(float x) {
    float y;
    asm("ex2.approx.ftz.f32 %0, %1;" : "=f"(y) : "f"(x));
    return y;
}
__device__ __forceinline__ uint32_t pack_h2(float a, float b) {
    __half2 t = __floats2half2_rn(a, b);
    return *(uint32_t*)&t;
}

// ---------------------------------------------------------------------------
// Merged conversions
// ---------------------------------------------------------------------------
__global__ __launch_bounds__(256) void conv_w4(
    const float* w0, const float* w1, const float* w2, const float* w3,
    __half* h0, __half* h1, __half* h2, __half* h3, int n4)
{
    const float* in; __half* hi;
    switch (blockIdx.y) {
        case 0:  in = w0; hi = h0; break;
        case 1:  in = w1; hi = h1; break;
        case 2:  in = w2; hi = h2; break;
        default: in = w3; hi = h3; break;
    }
    int idx = blockIdx.x * 256 + threadIdx.x;
    if (idx >= n4) return;
    float4 v = ((const float4*)in)[idx];
    __half h[4] = {__float2half_rn(v.x), __float2half_rn(v.y),
                   __float2half_rn(v.z), __float2half_rn(v.w)};
    ((uint2*)hi)[idx] = *(uint2*)h;
}

// Q -> hi+lo; K,V -> hi only
__global__ __launch_bounds__(256) void conv_a3(
    const float* a0, const float* a1, const float* a2,
    __half* h0, __half* l0, __half* h1, __half* h2, int n4)
{
    const float* in; __half *hi, *lo;
    switch (blockIdx.y) {
        case 0:  in = a0; hi = h0; lo = l0;      break;
        case 1:  in = a1; hi = h1; lo = nullptr; break;
        default: in = a2; hi = h2; lo = nullptr; break;
    }
    int idx = blockIdx.x * 256 + threadIdx.x;
    if (idx >= n4) return;
    float4 v = ((const float4*)in)[idx];
    float f[4] = {v.x, v.y, v.z, v.w};
    __half h[4];
#pragma unroll
    for (int i = 0; i < 4; ++i) h[i] = __float2half_rn(f[i]);
    ((uint2*)hi)[idx] = *(uint2*)h;
    if (lo) {
        __half l[4];
#pragma unroll
        for (int i = 0; i < 4; ++i)
            l[i] = __float2half_rn(f[i] - __half2float(h[i]));
        ((uint2*)lo)[idx] = *(uint2*)l;
    }
}

// ---------------------------------------------------------------------------
// HMMA projection GEMM body: C[8192,512] = X @ W^T + bias
// APROD = A-side products (2 = hi/lo, 1 = hi only). B hi-only.
// MODE 0: fp32 row-major out. MODE 1: fp16 hi(/lo) out, head layout, scaled.
// ---------------------------------------------------------------------------
#define ROWB   80
#define ARRSZ  10240

template <int MODE, int APROD>
__device__ __forceinline__ void proj_body(
    const __half* __restrict__ Ah, const __half* __restrict__ Al,
    const __half* __restrict__ Bh,
    const float* __restrict__ bias, float* __restrict__ outF,
    __half* __restrict__ outH, __half* __restrict__ outL, float scale,
    char* smem)
{
    constexpr int NARR = APROD + 1;
    constexpr int STG  = NARR * ARRSZ;

    const uint32_t sb = smem_u32(smem);
    const int tid  = threadIdx.x;
    const int lane = tid & 31;
    const int wid  = tid >> 5;
    const int warp_m = wid & 3;
    const int warp_n = wid >> 2;
    const int m0 = blockIdx.x * 128;
    const int n0 = blockIdx.y * 128;

    const int r0c = (tid + 0)   >> 2, s0c = tid & 3;
    const int r1c = (tid + 256) >> 2, s1c = tid & 3;

    const uint32_t a_off = (uint32_t)((warp_m * 32 + (lane & 15)) * ROWB + (lane >> 4) * 16);
    const uint32_t b_off = (uint32_t)((warp_n * 64 + (lane & 7) + 8 * (lane >> 4)) * ROWB
                                      + ((lane >> 3) & 1) * 16);

    float acc[2][8][4];
#pragma unroll
    for (int mi = 0; mi < 2; ++mi)
#pragma unroll
        for (int ni = 0; ni < 8; ++ni)
#pragma unroll
            for (int q = 0; q < 4; ++q) acc[mi][ni][q] = 0.0f;

    auto load_chunk = [&](int c, int stage) {
        const int k0 = c * 32;
        const uint32_t st = sb + stage * STG;
#pragma unroll
        for (int arr = 0; arr < NARR; ++arr) {
            const __half* base = (arr == NARR - 1) ? Bh : (arr == 0 ? Ah : Al);
            const int rbase = (arr == NARR - 1) ? n0 : m0;
            cp_async16(st + arr * ARRSZ + r0c * ROWB + s0c * 16,
                       base + (rbase + r0c) * ND + k0 + s0c * 8);
            cp_async16(st + arr * ARRSZ + r1c * ROWB + s1c * 16,
                       base + (rbase + r1c) * ND + k0 + s1c * 8);
        }
        cp_commit();
    };

    load_chunk(0, 0);

    for (int c = 0; c < 16; ++c) {
        const int stage = c & 1;
        if (c < 15) {
            load_chunk(c + 1, stage ^ 1);
            asm volatile("cp.async.wait_group 1;" ::: "memory");
        } else {
            asm volatile("cp.async.wait_group 0;" ::: "memory");
        }
        __syncthreads();

        const uint32_t st = sb + stage * STG;
#pragma unroll
        for (int ks = 0; ks < 2; ++ks) {
            const uint32_t kb = ks * 32;
            uint32_t ah[2][4], al[2][4];
#pragma unroll
            for (int mi = 0; mi < 2; ++mi) {
                uint32_t adr = st + a_off + mi * (16 * ROWB) + kb;
                ldsm_x4(adr, ah[mi][0], ah[mi][1], ah[mi][2], ah[mi][3]);
                if (APROD == 2)
                    ldsm_x4(adr + ARRSZ, al[mi][0], al[mi][1], al[mi][2], al[mi][3]);
            }
            uint32_t bh[8][2];
#pragma unroll
            for (int nb = 0; nb < 4; ++nb) {
                uint32_t adr = st + (NARR - 1) * ARRSZ + b_off + nb * (16 * ROWB) + kb;
                uint32_t t0, t1, t2, t3;
                ldsm_x4(adr, t0, t1, t2, t3);
                bh[nb*2][0] = t0; bh[nb*2][1] = t1; bh[nb*2+1][0] = t2; bh[nb*2+1][1] = t3;
            }
#pragma unroll
            for (int mi = 0; mi < 2; ++mi)
#pragma unroll
                for (int ni = 0; ni < 8; ++ni) {
                    mma16816(acc[mi][ni], ah[mi], bh[ni]);
                    if (APROD == 2) mma16816(acc[mi][ni], al[mi], bh[ni]);
                }
        }
        __syncthreads();
    }

    const int crow = lane >> 2;
    const int ccol = (lane & 3) * 2;
#pragma unroll
    for (int mi = 0; mi < 2; ++mi) {
#pragma unroll
        for (int half = 0; half < 2; ++half) {
            const int m = m0 + warp_m * 32 + mi * 16 + crow + half * 8;
            const int b = m >> 11, s = m & 2047;
#pragma unroll
            for (int ni = 0; ni < 8; ++ni) {
                const int n = n0 + warp_n * 64 + ni * 8 + ccol;
                float v0 = acc[mi][ni][half * 2 + 0] + bias[n];
                float v1 = acc[mi][ni][half * 2 + 1] + bias[n + 1];
                if (MODE == 1) {
                    v0 *= scale; v1 *= scale;
                    const int head = n >> 6, d = n & 63;
                    const int idx = ((b * NH + head) * NS + s) * NDH + d;
                    __half h0 = __float2half_rn(v0);
                    __half h1 = __float2half_rn(v1);
                    *(uint32_t*)&outH[idx] =
                        pack_h2(__half2float(h0), __half2float(h1));
                    if (outL) {
                        *(uint32_t*)&outL[idx] =
                            pack_h2(v0 - __half2float(h0), v1 - __half2float(h1));
                    }
                } else {
                    *(float2*)&outF[m * ND + n] = make_float2(v0, v1);
                }
            }
        }
    }
}

#define PROJ_SMEM_2 (2 * 3 * ARRSZ)   // APROD=2: 61440
#define PROJ_SMEM_1 (2 * 2 * ARRSZ)   // APROD=1: 40960

// Q projection: A hi/lo (2-product), fp16 hi+lo out
__global__ __launch_bounds__(256, 2) void proj_q(
    const __half* Ah, const __half* Al, const __half* Bh,
    const float* bias, __half* outH, __half* outL, float scale)
{
    extern __shared__ char smem[];
    proj_body<1, 2>(Ah, Al, Bh, bias, nullptr, outH, outL, scale, smem);
}

// K+V projections fused (blockIdx.z selects): A hi only, fp16 hi out
__global__ __launch_bounds__(256, 2) void proj_kv(
    const __half* AhK, const __half* BhK, const float* biasK, __half* outK,
    const __half* AhV, const __half* BhV, const float* biasV, __half* outV)
{
    extern __shared__ char smem[];
    const __half *Ah, *Bh; const float* bias; __half* outH;
    if (blockIdx.z == 0) { Ah = AhK; Bh = BhK; bias = biasK; outH = outK; }
    else                 { Ah = AhV; Bh = BhV; bias = biasV; outH = outV; }
    proj_body<1, 1>(Ah, nullptr, Bh, bias, nullptr, outH, nullptr, 1.0f, smem);
}

// Output projection: single product, fp32 out
__global__ __launch_bounds__(256, 2) void proj_o(
    const __half* Ah, const __half* Bh, const float* bias, float* outF)
{
    extern __shared__ char smem[];
    proj_body<0, 1>(Ah, nullptr, Bh, bias, outF, nullptr, nullptr, 1.0f, smem);
}

// ---------------------------------------------------------------------------
// HMMA flash attention (unchanged from R9). CTA = 128 q rows x one (b,h),
// 8 warps, KV tile 64 double-buffered, 2 CTAs/SM. q hi/lo, k/v hi, P hi.
// q pre-scaled by 0.125*log2(e); softmax in log2 domain. ctx hi only.
// ---------------------------------------------------------------------------
#define QROWB 144
#define QARR  18432
#define KARRA 9216
#define KVSTG (2 * KARRA)
#define ATTN_SMEM (2 * QARR + 2 * KVSTG)   // 73728

__global__ __launch_bounds__(256, 2) void attn_hmma(
    const __half* __restrict__ qh, const __half* __restrict__ ql,
    const __half* __restrict__ kh, const __half* __restrict__ vh,
    __half* __restrict__ ch,
    const void* __restrict__ masked_raw)
{
    extern __shared__ char smem[];
    const uint32_t sb = smem_u32(smem);
    const int tid  = threadIdx.x;
    const int lane = tid & 31;
    const int wid  = tid >> 5;
    const int bh   = blockIdx.y;
    const int b    = bh >> 3;
    const int h    = bh & 7;
    const int q0   = blockIdx.x << 7;
    const int gbase = bh * NS * NDH;

    int len;
    {
        const long long* ml = (const long long*)masked_raw;
        long long probe = ml[0];
        if (probe >= 1 && probe <= NS) len = (int)ml[b];
        else                           len = ((const int*)masked_raw)[b];
    }
    const int ntiles = (len + 63) >> 6;

#pragma unroll
    for (int i = 0; i < 4; ++i) {
        int c = tid + i * 256;
        int r = c >> 3, blk = c & 7;
        const int src = gbase + (q0 + r) * NDH + blk * 8;
        *(uint4*)(smem + r * QROWB + blk * 16)        = *(const uint4*)(qh + src);
        *(uint4*)(smem + QARR + r * QROWB + blk * 16) = *(const uint4*)(ql + src);
    }

    auto load_kv = [&](int t, int stg) {
        const uint32_t s0 = sb + 2 * QARR + stg * KVSTG;
        const int gk = gbase + (t << 6) * NDH;
#pragma unroll
        for (int i = 0; i < 2; ++i) {
            int c = tid + i * 256;
            int r = c >> 3, blk = c & 7;
            const uint32_t dst = s0 + r * QROWB + blk * 16;
            const int src = gk + r * NDH + blk * 8;
            cp_async16(dst,         kh + src);
            cp_async16(dst + KARRA, vh + src);
        }
        cp_commit();
    };

    load_kv(0, 0);
    __syncthreads();

    uint32_t qfh[4][4], qfl[4][4];
    {
        const uint32_t qa = sb + (wid * 16 + (lane & 15)) * QROWB + (lane >> 4) * 16;
#pragma unroll
        for (int ks = 0; ks < 4; ++ks) {
            ldsm_x4(qa + ks * 32,        qfh[ks][0], qfh[ks][1], qfh[ks][2], qfh[ks][3]);
            ldsm_x4(qa + ks * 32 + QARR, qfl[ks][0], qfl[ks][1], qfl[ks][2], qfl[ks][3]);
        }
    }

    float m0r = -1e30f, m1r = -1e30f, lsum0 = 0.0f, lsum1 = 0.0f;
    float o[8][4];
#pragma unroll
    for (int di = 0; di < 8; ++di)
#pragma unroll
        for (int q = 0; q < 4; ++q) o[di][q] = 0.0f;

    for (int t = 0; t < ntiles; ++t) {
        const int stg = t & 1;
        if (t + 1 < ntiles) {
            load_kv(t + 1, stg ^ 1);
            asm volatile("cp.async.wait_group 1;" ::: "memory");
        } else {
            asm volatile("cp.async.wait_group 0;" ::: "memory");
        }
        __syncthreads();

        const uint32_t kbase = sb + 2 * QARR + stg * KVSTG;

        float s[8][4];
#pragma unroll
        for (int ni = 0; ni < 8; ++ni)
#pragma unroll
            for (int q = 0; q < 4; ++q) s[ni][q] = 0.0f;

#pragma unroll
        for (int ks = 0; ks < 4; ++ks) {
#pragma unroll
            for (int nb = 0; nb < 4; ++nb) {
                const uint32_t adr = kbase
                    + (nb * 16 + (lane & 7) + 8 * (lane >> 4)) * QROWB
                    + ((lane >> 3) & 1) * 16 + ks * 32;
                uint32_t t0, t1, t2, t3;
                ldsm_x4(adr, t0, t1, t2, t3);
                uint32_t bh0[2] = {t0, t1}, bh1[2] = {t2, t3};
                mma16816(s[nb*2],   qfh[ks], bh0);
                mma16816(s[nb*2],   qfl[ks], bh0);
                mma16816(s[nb*2+1], qfh[ks], bh1);
                mma16816(s[nb*2+1], qfl[ks], bh1);
            }
        }

        const int kv0 = t << 6;
        const int cb  = kv0 + 2 * (lane & 3);
        float tmax0 = -1e30f, tmax1 = -1e30f;
#pragma unroll
        for (int ni = 0; ni < 8; ++ni) {
            const int c0 = cb + 8 * ni;
            if (c0     >= len) { s[ni][0] = -1e30f; s[ni][2] = -1e30f; }
            if (c0 + 1 >= len) { s[ni][1] = -1e30f; s[ni][3] = -1e30f; }
            tmax0 = fmaxf(tmax0, fmaxf(s[ni][0], s[ni][1]));
            tmax1 = fmaxf(tmax1, fmaxf(s[ni][2], s[ni][3]));
        }
        tmax0 = fmaxf(tmax0, __shfl_xor_sync(0xffffffffu, tmax0, 1));
        tmax0 = fmaxf(tmax0, __shfl_xor_sync(0xffffffffu, tmax0, 2));
        tmax1 = fmaxf(tmax1, __shfl_xor_sync(0xffffffffu, tmax1, 1));
        tmax1 = fmaxf(tmax1, __shfl_xor_sync(0xffffffffu, tmax1, 2));

        const float mn0 = fmaxf(m0r, tmax0);
        const float mn1 = fmaxf(m1r, tmax1);
        const float sc0 = ex2(m0r - mn0);
        const float sc1 = ex2(m1r - mn1);
        m0r = mn0; m1r = mn1;

        float ps0 = 0.0f, ps1 = 0.0f;
#pragma unroll
        for (int ni = 0; ni < 8; ++ni) {
            float p0 = ex2(s[ni][0] - mn0);
            float p1 = ex2(s[ni][1] - mn0);
            float p2 = ex2(s[ni][2] - mn1);
            float p3 = ex2(s[ni][3] - mn1);
            ps0 += p0 + p1;
            ps1 += p2 + p3;
            s[ni][0] = __uint_as_float(pack_h2(p0, p1));
            s[ni][2] = __uint_as_float(pack_h2(p2, p3));
        }
        ps0 += __shfl_xor_sync(0xffffffffu, ps0, 1);
        ps0 += __shfl_xor_sync(0xffffffffu, ps0, 2);
        ps1 += __shfl_xor_sync(0xffffffffu, ps1, 1);
        ps1 += __shfl_xor_sync(0xffffffffu, ps1, 2);
        lsum0 = lsum0 * sc0 + ps0;
        lsum1 = lsum1 * sc1 + ps1;
#pragma unroll
        for (int di = 0; di < 8; ++di) {
            o[di][0] *= sc0; o[di][1] *= sc0;
            o[di][2] *= sc1; o[di][3] *= sc1;
        }

        const uint32_t vbase = kbase + KARRA;
#pragma unroll
        for (int ks2 = 0; ks2 < 4; ++ks2) {
            uint32_t Ahf[4] = {
                __float_as_uint(s[2*ks2][0]),   __float_as_uint(s[2*ks2][2]),
                __float_as_uint(s[2*ks2+1][0]), __float_as_uint(s[2*ks2+1][2]) };
#pragma unroll
            for (int db = 0; db < 4; ++db) {
                const uint32_t adr = vbase
                    + (ks2 * 16 + (lane & 7) + 8 * ((lane >> 3) & 1)) * QROWB
                    + ((lane >> 4) & 1) * 16 + db * 32;
                uint32_t t0, t1, t2, t3;
                ldsm_x4_t(adr, t0, t1, t2, t3);
                uint32_t vh0[2] = {t0, t1}, vh1[2] = {t2, t3};
                mma16816(o[db*2],   Ahf, vh0);
                mma16816(o[db*2+1], Ahf, vh1);
            }
        }
        __syncthreads();
    }

    const float inv0 = 1.0f / lsum0;
    const float inv1 = 1.0f / lsum1;
    const int r  = lane >> 2;
    const int dc = 2 * (lane & 3);
    const int qrow0 = q0 + wid * 16 + r;
#pragma unroll
    for (int di = 0; di < 8; ++di) {
        const int d = 8 * di + dc;
        *(uint32_t*)&ch[((b * NS + qrow0) * ND) + h * NDH + d] =
            pack_h2(o[di][0] * inv0, o[di][1] * inv0);
        *(uint32_t*)&ch[((b * NS + qrow0 + 8) * ND) + h * NDH + d] =
            pack_h2(o[di][2] * inv1, o[di][3] * inv1);
    }
}

// ---------------------------------------------------------------------------
extern "C" void kernel_launch(void* const* d_in, const int* in_sizes, int n_in,
                              void* d_out, int out_size)
{
    (void)in_sizes; (void)n_in; (void)out_size;
    const float* Q  = (const float*)d_in[0];
    const float* K  = (const float*)d_in[1];
    const float* V  = (const float*)d_in[2];
    const float* Wq = (const float*)d_in[3];
    const float* bq = (const float*)d_in[4];
    const float* Wk = (const float*)d_in[5];
    const float* bk = (const float*)d_in[6];
    const float* Wv = (const float*)d_in[7];
    const float* bv = (const float*)d_in[8];
    const float* Wo = (const float*)d_in[9];
    const float* bo = (const float*)d_in[10];
    const void*  mk = d_in[11];
    float* out = (float*)d_out;

    __half *pqh, *pql, *pkh, *pvh, *pch, *pah, *pal, *pwh;
    cudaGetSymbolAddress((void**)&pqh, g_qh);
    cudaGetSymbolAddress((void**)&pql, g_ql);
    cudaGetSymbolAddress((void**)&pkh, g_kh);
    cudaGetSymbolAddress((void**)&pvh, g_vh);
    cudaGetSymbolAddress((void**)&pch, g_ch);
    cudaGetSymbolAddress((void**)&pah, g_ah);
    cudaGetSymbolAddress((void**)&pal, g_al);
    cudaGetSymbolAddress((void**)&pwh, g_wh);

    const int NACT = NB * NS * ND;   // 4194304
    const int NW   = ND * ND;        // 262144
    const int nx4 = NACT / 4;
    const int nw4 = NW / 4;

    cudaFuncSetAttribute((const void*)proj_q,
                         cudaFuncAttributeMaxDynamicSharedMemorySize, PROJ_SMEM_2);
    cudaFuncSetAttribute((const void*)proj_kv,
                         cudaFuncAttributeMaxDynamicSharedMemorySize, PROJ_SMEM_1);
    cudaFuncSetAttribute((const void*)proj_o,
                         cudaFuncAttributeMaxDynamicSharedMemorySize, PROJ_SMEM_1);
    cudaFuncSetAttribute((const void*)attn_hmma,
                         cudaFuncAttributeMaxDynamicSharedMemorySize, ATTN_SMEM);

    const float QSCALE = 0.125f * 1.4426950408889634f;  // 1/sqrt(64) * log2(e)

    // 1) weight hi conversions (4 in one launch)
    conv_w4<<<dim3((nw4 + 255) / 256, 4), 256>>>(
        Wq, Wk, Wv, Wo, pwh, pwh + NW, pwh + 2 * NW, pwh + 3 * NW, nw4);
    // 2) activation conversions: Q hi/lo, K hi, V hi (one launch)
    conv_a3<<<dim3((nx4 + 255) / 256, 3), 256>>>(
        Q, K, V, pah, pal, pah + NACT, pah + 2 * NACT, nx4);
    // 3) Q projection (2-product)
    proj_q<<<dim3(64, 4), 256, PROJ_SMEM_2>>>(
        pah, pal, pwh, bq, pqh, pql, QSCALE);
    // 4) K+V projections fused (single-product)
    proj_kv<<<dim3(64, 4, 2), 256, PROJ_SMEM_1>>>(
        pah + NACT,     pwh + NW,     bk, pkh,
        pah + 2 * NACT, pwh + 2 * NW, bv, pvh);
    // 5) attention
    attn_hmma<<<dim3(NS / 128, NB * NH), 256, ATTN_SMEM>>>(
        pqh, pql, pkh, pvh, pch, mk);
    // 6) output projection (single-product)
    proj_o<<<dim3(64, 4), 256, PROJ_SMEM_1>>>(
        pch, pwh + 3 * NW, bo, out);
}

// round 11
// speedup vs baseline: 2.5595x; 1.2913x over previous
#include <cuda_runtime.h>
#include <cuda_fp16.h>
#include <cstdint>

#define NB  4
#define NS  2048
#define ND  512
#define NH  8
#define NDH 64

// ---------------------------------------------------------------------------
// Scratch (device globals: allocation-free rule)
// ---------------------------------------------------------------------------
__device__ __half g_qh[NB * NH * NS * NDH];   // hi only (pre-scaled)
__device__ __half g_kh[NB * NH * NS * NDH];   // hi only
__device__ __half g_vh[NB * NH * NS * NDH];   // hi only
__device__ __half g_ch[NB * NS * ND];         // ctx hi only
__device__ __half g_ah[3][NB * NS * ND];      // Q/K/V activation hi
__device__ __half g_wh[4][ND * ND];           // Wq,Wk,Wv,Wo hi

// ---------------------------------------------------------------------------
__device__ __forceinline__ uint32_t smem_u32(const void* p) {
    uint32_t a;
    asm("{ .reg .u64 t; cvta.to.shared.u64 t, %1; cvt.u32.u64 %0, t; }"
        : "=r"(a) : "l"(p));
    return a;
}
__device__ __forceinline__ void cp_async16(uint32_t dst, const void* src) {
    asm volatile("cp.async.ca.shared.global [%0], [%1], 16;"
                 :: "r"(dst), "l"(src) : "memory");
}
__device__ __forceinline__ void cp_commit() {
    asm volatile("cp.async.commit_group;" ::: "memory");
}
__device__ __forceinline__ void ldsm_x4(uint32_t addr, uint32_t& r0, uint32_t& r1,
                                        uint32_t& r2, uint32_t& r3) {
    asm volatile("ldmatrix.sync.aligned.m8n8.x4.shared.b16 {%0,%1,%2,%3}, [%4];"
                 : "=r"(r0), "=r"(r1), "=r"(r2), "=r"(r3) : "r"(addr));
}
__device__ __forceinline__ void ldsm_x4_t(uint32_t addr, uint32_t& r0, uint32_t& r1,
                                          uint32_t& r2, uint32_t& r3) {
    asm volatile("ldmatrix.sync.aligned.m8n8.x4.trans.shared.b16 {%0,%1,%2,%3}, [%4];"
                 : "=r"(r0), "=r"(r1), "=r"(r2), "=r"(r3) : "r"(addr));
}
__device__ __forceinline__ void mma16816(float* c, const uint32_t* a, const uint32_t* b) {
    asm volatile(
        "mma.sync.aligned.m16n8k16.row.col.f32.f16.f16.f32 "
        "{%0,%1,%2,%3}, {%4,%5,%6,%7}, {%8,%9}, {%0,%1,%2,%3};"
        : "+f"(c[0]), "+f"(c[1]), "+f"(c[2]), "+f"(c[3])
        : "r"(a[0]), "r"(a[1]), "r"(a[2]), "r"(a[3]), "r"(b[0]), "r"(b[1]));
}
__device__ __forceinline__ float ex2(float x) {
    float y;
    asm("ex2.approx.ftz.f32 %0, %1;" : "=f"(y) : "f"(x));
    return y;
}
__device__ __forceinline__ uint32_t pack_h2(float a, float b) {
    __half2 t = __floats2half2_rn(a, b);
    return *(uint32_t*)&t;
}

// ---------------------------------------------------------------------------
// Merged conversions (fp32 -> fp16 hi, scalar-switch on blockIdx.y)
// ---------------------------------------------------------------------------
__global__ __launch_bounds__(256) void conv_w4(
    const float* w0, const float* w1, const float* w2, const float* w3,
    __half* h0, __half* h1, __half* h2, __half* h3, int n4)
{
    const float* in; __half* hi;
    switch (blockIdx.y) {
        case 0:  in = w0; hi = h0; break;
        case 1:  in = w1; hi = h1; break;
        case 2:  in = w2; hi = h2; break;
        default: in = w3; hi = h3; break;
    }
    int idx = blockIdx.x * 256 + threadIdx.x;
    if (idx >= n4) return;
    float4 v = ((const float4*)in)[idx];
    __half h[4] = {__float2half_rn(v.x), __float2half_rn(v.y),
                   __float2half_rn(v.z), __float2half_rn(v.w)};
    ((uint2*)hi)[idx] = *(uint2*)h;
}

__global__ __launch_bounds__(256) void conv_a3(
    const float* a0, const float* a1, const float* a2,
    __half* h0, __half* h1, __half* h2, int n4)
{
    const float* in; __half* hi;
    switch (blockIdx.y) {
        case 0:  in = a0; hi = h0; break;
        case 1:  in = a1; hi = h1; break;
        default: in = a2; hi = h2; break;
    }
    int idx = blockIdx.x * 256 + threadIdx.x;
    if (idx >= n4) return;
    float4 v = ((const float4*)in)[idx];
    __half h[4] = {__float2half_rn(v.x), __float2half_rn(v.y),
                   __float2half_rn(v.z), __float2half_rn(v.w)};
    ((uint2*)hi)[idx] = *(uint2*)h;
}

// ---------------------------------------------------------------------------
// HMMA projection GEMM body: C[8192,512] = X @ W^T + bias
// Single product (A hi x B hi), BK=64 chunks, double-buffered, 2 CTAs/SM.
// MODE 0: fp32 row-major out. MODE 1: fp16 hi out, head layout, scaled.
// ---------------------------------------------------------------------------
#define ROWB   144           // 64 halves (128B) + 16B pad; rows conflict-free
#define ARRSZ  (128 * ROWB)  // 18432
#define STG    (2 * ARRSZ)   // A + B per stage
#define PROJ_SMEM (2 * STG)  // 73728

template <int MODE>
__device__ __forceinline__ void proj_body(
    const __half* __restrict__ Ah, const __half* __restrict__ Bh,
    const float* __restrict__ bias, float* __restrict__ outF,
    __half* __restrict__ outH, float scale, char* smem)
{
    const uint32_t sb = smem_u32(smem);
    const int tid  = threadIdx.x;
    const int lane = tid & 31;
    const int wid  = tid >> 5;
    const int warp_m = wid & 3;
    const int warp_n = wid >> 2;
    const int m0 = blockIdx.x * 128;
    const int n0 = blockIdx.y * 128;

    const uint32_t a_off = (uint32_t)((warp_m * 32 + (lane & 15)) * ROWB + (lane >> 4) * 16);
    const uint32_t b_off = (uint32_t)((warp_n * 64 + (lane & 7) + 8 * (lane >> 4)) * ROWB
                                      + ((lane >> 3) & 1) * 16);

    float acc[2][8][4];
#pragma unroll
    for (int mi = 0; mi < 2; ++mi)
#pragma unroll
        for (int ni = 0; ni < 8; ++ni)
#pragma unroll
            for (int q = 0; q < 4; ++q) acc[mi][ni][q] = 0.0f;

    auto load_chunk = [&](int c, int stage) {
        const int k0 = c * 64;
        const uint32_t st = sb + stage * STG;
#pragma unroll
        for (int i = 0; i < 4; ++i) {
            const int c2 = tid + i * 256;     // 0..1023
            const int r  = c2 >> 3;           // row 0..127
            const int g  = c2 & 7;            // 16B group 0..7
            cp_async16(st + r * ROWB + g * 16,
                       Ah + (m0 + r) * ND + k0 + g * 8);
            cp_async16(st + ARRSZ + r * ROWB + g * 16,
                       Bh + (n0 + r) * ND + k0 + g * 8);
        }
        cp_commit();
    };

    load_chunk(0, 0);

    for (int c = 0; c < 8; ++c) {
        const int stage = c & 1;
        if (c < 7) {
            load_chunk(c + 1, stage ^ 1);
            asm volatile("cp.async.wait_group 1;" ::: "memory");
        } else {
            asm volatile("cp.async.wait_group 0;" ::: "memory");
        }
        __syncthreads();

        const uint32_t st = sb + stage * STG;
#pragma unroll
        for (int ks = 0; ks < 4; ++ks) {
            const uint32_t kb = ks * 32;
            uint32_t ah[2][4];
#pragma unroll
            for (int mi = 0; mi < 2; ++mi) {
                uint32_t adr = st + a_off + mi * (16 * ROWB) + kb;
                ldsm_x4(adr, ah[mi][0], ah[mi][1], ah[mi][2], ah[mi][3]);
            }
#pragma unroll
            for (int nb = 0; nb < 4; ++nb) {
                uint32_t adr = st + ARRSZ + b_off + nb * (16 * ROWB) + kb;
                uint32_t t0, t1, t2, t3;
                ldsm_x4(adr, t0, t1, t2, t3);
                uint32_t bhA[2] = {t0, t1}, bhB[2] = {t2, t3};
#pragma unroll
                for (int mi = 0; mi < 2; ++mi) {
                    mma16816(acc[mi][nb*2],   ah[mi], bhA);
                    mma16816(acc[mi][nb*2+1], ah[mi], bhB);
                }
            }
        }
        __syncthreads();
    }

    const int crow = lane >> 2;
    const int ccol = (lane & 3) * 2;
#pragma unroll
    for (int mi = 0; mi < 2; ++mi) {
#pragma unroll
        for (int half = 0; half < 2; ++half) {
            const int m = m0 + warp_m * 32 + mi * 16 + crow + half * 8;
            const int b = m >> 11, s = m & 2047;
#pragma unroll
            for (int ni = 0; ni < 8; ++ni) {
                const int n = n0 + warp_n * 64 + ni * 8 + ccol;
                float v0 = acc[mi][ni][half * 2 + 0] + bias[n];
                float v1 = acc[mi][ni][half * 2 + 1] + bias[n + 1];
                if (MODE == 1) {
                    v0 *= scale; v1 *= scale;
                    const int head = n >> 6, d = n & 63;
                    const int idx = ((b * NH + head) * NS + s) * NDH + d;
                    *(uint32_t*)&outH[idx] = pack_h2(v0, v1);
                } else {
                    *(float2*)&outF[m * ND + n] = make_float2(v0, v1);
                }
            }
        }
    }
}

// Fused Q/K/V projections (blockIdx.z selects), fp16 hi out, head layout
__global__ __launch_bounds__(256, 2) void proj_qkv(
    const __half* AhQ, const __half* BhQ, const float* biasQ, __half* outQ, float scaleQ,
    const __half* AhK, const __half* BhK, const float* biasK, __half* outK,
    const __half* AhV, const __half* BhV, const float* biasV, __half* outV)
{
    extern __shared__ char smem[];
    const __half *Ah, *Bh; const float* bias; __half* outH; float scale;
    if (blockIdx.z == 0)      { Ah = AhQ; Bh = BhQ; bias = biasQ; outH = outQ; scale = scaleQ; }
    else if (blockIdx.z == 1) { Ah = AhK; Bh = BhK; bias = biasK; outH = outK; scale = 1.0f; }
    else                      { Ah = AhV; Bh = BhV; bias = biasV; outH = outV; scale = 1.0f; }
    proj_body<1>(Ah, Bh, bias, nullptr, outH, scale, smem);
}

// Output projection, fp32 out
__global__ __launch_bounds__(256, 2) void proj_o(
    const __half* Ah, const __half* Bh, const float* bias, float* outF)
{
    extern __shared__ char smem[];
    proj_body<0>(Ah, Bh, bias, outF, nullptr, 1.0f, smem);
}

// ---------------------------------------------------------------------------
// HMMA flash attention. CTA = 128 q rows x one (b,h), 8 warps, KV tile 64
// double-buffered, 2 CTAs/SM. q/k/v all fp16 hi; P hi; ctx hi.
// q pre-scaled by 0.125*log2(e); softmax in log2 domain.
// ---------------------------------------------------------------------------
#define QROWB 144
#define QARR  18432
#define KARRA 9216
#define KVSTG (2 * KARRA)
#define ATTN_SMEM (QARR + 2 * KVSTG)   // 55296

__global__ __launch_bounds__(256, 2) void attn_hmma(
    const __half* __restrict__ qh,
    const __half* __restrict__ kh, const __half* __restrict__ vh,
    __half* __restrict__ ch,
    const void* __restrict__ masked_raw)
{
    extern __shared__ char smem[];
    const uint32_t sb = smem_u32(smem);
    const int tid  = threadIdx.x;
    const int lane = tid & 31;
    const int wid  = tid >> 5;
    const int bh   = blockIdx.y;
    const int b    = bh >> 3;
    const int h    = bh & 7;
    const int q0   = blockIdx.x << 7;
    const int gbase = bh * NS * NDH;

    int len;
    {
        const long long* ml = (const long long*)masked_raw;
        long long probe = ml[0];
        if (probe >= 1 && probe <= NS) len = (int)ml[b];
        else                           len = ((const int*)masked_raw)[b];
    }
    const int ntiles = (len + 63) >> 6;

    // Load Q hi into smem (128 rows x 8 groups = 1024 lines)
#pragma unroll
    for (int i = 0; i < 4; ++i) {
        int c = tid + i * 256;
        int r = c >> 3, blk = c & 7;
        *(uint4*)(smem + r * QROWB + blk * 16) =
            *(const uint4*)(qh + gbase + (q0 + r) * NDH + blk * 8);
    }

    auto load_kv = [&](int t, int stg) {
        const uint32_t s0 = sb + QARR + stg * KVSTG;
        const int gk = gbase + (t << 6) * NDH;
#pragma unroll
        for (int i = 0; i < 2; ++i) {
            int c = tid + i * 256;
            int r = c >> 3, blk = c & 7;
            const uint32_t dst = s0 + r * QROWB + blk * 16;
            const int src = gk + r * NDH + blk * 8;
            cp_async16(dst,         kh + src);
            cp_async16(dst + KARRA, vh + src);
        }
        cp_commit();
    };

    load_kv(0, 0);
    __syncthreads();

    uint32_t qf[4][4];
    {
        const uint32_t qa = sb + (wid * 16 + (lane & 15)) * QROWB + (lane >> 4) * 16;
#pragma unroll
        for (int ks = 0; ks < 4; ++ks)
            ldsm_x4(qa + ks * 32, qf[ks][0], qf[ks][1], qf[ks][2], qf[ks][3]);
    }

    float m0r = -1e30f, m1r = -1e30f, lsum0 = 0.0f, lsum1 = 0.0f;
    float o[8][4];
#pragma unroll
    for (int di = 0; di < 8; ++di)
#pragma unroll
        for (int q = 0; q < 4; ++q) o[di][q] = 0.0f;

    for (int t = 0; t < ntiles; ++t) {
        const int stg = t & 1;
        if (t + 1 < ntiles) {
            load_kv(t + 1, stg ^ 1);
            asm volatile("cp.async.wait_group 1;" ::: "memory");
        } else {
            asm volatile("cp.async.wait_group 0;" ::: "memory");
        }
        __syncthreads();

        const uint32_t kbase = sb + QARR + stg * KVSTG;

        // ---- S = Q K^T (per-warp 16 x 64, single product) ----
        float s[8][4];
#pragma unroll
        for (int ni = 0; ni < 8; ++ni)
#pragma unroll
            for (int q = 0; q < 4; ++q) s[ni][q] = 0.0f;

#pragma unroll
        for (int ks = 0; ks < 4; ++ks) {
#pragma unroll
            for (int nb = 0; nb < 4; ++nb) {
                const uint32_t adr = kbase
                    + (nb * 16 + (lane & 7) + 8 * (lane >> 4)) * QROWB
                    + ((lane >> 3) & 1) * 16 + ks * 32;
                uint32_t t0, t1, t2, t3;
                ldsm_x4(adr, t0, t1, t2, t3);
                uint32_t bh0[2] = {t0, t1}, bh1[2] = {t2, t3};
                mma16816(s[nb*2],   qf[ks], bh0);
                mma16816(s[nb*2+1], qf[ks], bh1);
            }
        }

        // ---- mask + online softmax (log2 domain) ----
        const int kv0 = t << 6;
        const int cb  = kv0 + 2 * (lane & 3);
        float tmax0 = -1e30f, tmax1 = -1e30f;
#pragma unroll
        for (int ni = 0; ni < 8; ++ni) {
            const int c0 = cb + 8 * ni;
            if (c0     >= len) { s[ni][0] = -1e30f; s[ni][2] = -1e30f; }
            if (c0 + 1 >= len) { s[ni][1] = -1e30f; s[ni][3] = -1e30f; }
            tmax0 = fmaxf(tmax0, fmaxf(s[ni][0], s[ni][1]));
            tmax1 = fmaxf(tmax1, fmaxf(s[ni][2], s[ni][3]));
        }
        tmax0 = fmaxf(tmax0, __shfl_xor_sync(0xffffffffu, tmax0, 1));
        tmax0 = fmaxf(tmax0, __shfl_xor_sync(0xffffffffu, tmax0, 2));
        tmax1 = fmaxf(tmax1, __shfl_xor_sync(0xffffffffu, tmax1, 1));
        tmax1 = fmaxf(tmax1, __shfl_xor_sync(0xffffffffu, tmax1, 2));

        const float mn0 = fmaxf(m0r, tmax0);
        const float mn1 = fmaxf(m1r, tmax1);
        const float sc0 = ex2(m0r - mn0);
        const float sc1 = ex2(m1r - mn1);
        m0r = mn0; m1r = mn1;

        float ps0 = 0.0f, ps1 = 0.0f;
#pragma unroll
        for (int ni = 0; ni < 8; ++ni) {
            float p0 = ex2(s[ni][0] - mn0);
            float p1 = ex2(s[ni][1] - mn0);
            float p2 = ex2(s[ni][2] - mn1);
            float p3 = ex2(s[ni][3] - mn1);
            ps0 += p0 + p1;
            ps1 += p2 + p3;
            s[ni][0] = __uint_as_float(pack_h2(p0, p1));
            s[ni][2] = __uint_as_float(pack_h2(p2, p3));
        }
        ps0 += __shfl_xor_sync(0xffffffffu, ps0, 1);
        ps0 += __shfl_xor_sync(0xffffffffu, ps0, 2);
        ps1 += __shfl_xor_sync(0xffffffffu, ps1, 1);
        ps1 += __shfl_xor_sync(0xffffffffu, ps1, 2);
        lsum0 = lsum0 * sc0 + ps0;
        lsum1 = lsum1 * sc1 + ps1;
#pragma unroll
        for (int di = 0; di < 8; ++di) {
            o[di][0] *= sc0; o[di][1] *= sc0;
            o[di][2] *= sc1; o[di][3] *= sc1;
        }

        // ---- O += P V ----
        const uint32_t vbase = kbase + KARRA;
#pragma unroll
        for (int ks2 = 0; ks2 < 4; ++ks2) {
            uint32_t Ahf[4] = {
                __float_as_uint(s[2*ks2][0]),   __float_as_uint(s[2*ks2][2]),
                __float_as_uint(s[2*ks2+1][0]), __float_as_uint(s[2*ks2+1][2]) };
#pragma unroll
            for (int db = 0; db < 4; ++db) {
                const uint32_t adr = vbase
                    + (ks2 * 16 + (lane & 7) + 8 * ((lane >> 3) & 1)) * QROWB
                    + ((lane >> 4) & 1) * 16 + db * 32;
                uint32_t t0, t1, t2, t3;
                ldsm_x4_t(adr, t0, t1, t2, t3);
                uint32_t vh0[2] = {t0, t1}, vh1[2] = {t2, t3};
                mma16816(o[db*2],   Ahf, vh0);
                mma16816(o[db*2+1], Ahf, vh1);
            }
        }
        __syncthreads();
    }

    // ---- normalize + write ctx hi [B,S,D] ----
    const float inv0 = 1.0f / lsum0;
    const float inv1 = 1.0f / lsum1;
    const int r  = lane >> 2;
    const int dc = 2 * (lane & 3);
    const int qrow0 = q0 + wid * 16 + r;
#pragma unroll
    for (int di = 0; di < 8; ++di) {
        const int d = 8 * di + dc;
        *(uint32_t*)&ch[((b * NS + qrow0) * ND) + h * NDH + d] =
            pack_h2(o[di][0] * inv0, o[di][1] * inv0);
        *(uint32_t*)&ch[((b * NS + qrow0 + 8) * ND) + h * NDH + d] =
            pack_h2(o[di][2] * inv1, o[di][3] * inv1);
    }
}

// ---------------------------------------------------------------------------
extern "C" void kernel_launch(void* const* d_in, const int* in_sizes, int n_in,
                              void* d_out, int out_size)
{
    (void)in_sizes; (void)n_in; (void)out_size;
    const float* Q  = (const float*)d_in[0];
    const float* K  = (const float*)d_in[1];
    const float* V  = (const float*)d_in[2];
    const float* Wq = (const float*)d_in[3];
    const float* bq = (const float*)d_in[4];
    const float* Wk = (const float*)d_in[5];
    const float* bk = (const float*)d_in[6];
    const float* Wv = (const float*)d_in[7];
    const float* bv = (const float*)d_in[8];
    const float* Wo = (const float*)d_in[9];
    const float* bo = (const float*)d_in[10];
    const void*  mk = d_in[11];
    float* out = (float*)d_out;

    __half *pqh, *pkh, *pvh, *pch, *pah, *pwh;
    cudaGetSymbolAddress((void**)&pqh, g_qh);
    cudaGetSymbolAddress((void**)&pkh, g_kh);
    cudaGetSymbolAddress((void**)&pvh, g_vh);
    cudaGetSymbolAddress((void**)&pch, g_ch);
    cudaGetSymbolAddress((void**)&pah, g_ah);
    cudaGetSymbolAddress((void**)&pwh, g_wh);

    const int NACT = NB * NS * ND;   // 4194304
    const int NW   = ND * ND;        // 262144
    const int nx4 = NACT / 4;
    const int nw4 = NW / 4;

    cudaFuncSetAttribute((const void*)proj_qkv,
                         cudaFuncAttributeMaxDynamicSharedMemorySize, PROJ_SMEM);
    cudaFuncSetAttribute((const void*)proj_o,
                         cudaFuncAttributeMaxDynamicSharedMemorySize, PROJ_SMEM);
    cudaFuncSetAttribute((const void*)attn_hmma,
                         cudaFuncAttributeMaxDynamicSharedMemorySize, ATTN_SMEM);

    const float QSCALE = 0.125f * 1.4426950408889634f;  // 1/sqrt(64) * log2(e)

    // 1) weight hi conversions (4 in one launch)
    conv_w4<<<dim3((nw4 + 255) / 256, 4), 256>>>(
        Wq, Wk, Wv, Wo, pwh, pwh + NW, pwh + 2 * NW, pwh + 3 * NW, nw4);
    // 2) activation hi conversions (3 in one launch)
    conv_a3<<<dim3((nx4 + 255) / 256, 3), 256>>>(
        Q, K, V, pah, pah + NACT, pah + 2 * NACT, nx4);
    // 3) fused Q/K/V projections (single product each)
    proj_qkv<<<dim3(64, 4, 3), 256, PROJ_SMEM>>>(
        pah,            pwh,          bq, pqh, QSCALE,
        pah + NACT,     pwh + NW,     bk, pkh,
        pah + 2 * NACT, pwh + 2 * NW, bv, pvh);
    // 4) attention
    attn_hmma<<<dim3(NS / 128, NB * NH), 256, ATTN_SMEM>>>(
        pqh, pkh, pvh, pch, mk);
    // 5) output projection
    proj_o<<<dim3(64, 4), 256, PROJ_SMEM>>>(
        pch, pwh + 3 * NW, bo, out);
}

// round 12
// speedup vs baseline: 2.5719x; 1.0049x over previous
#include <cuda_runtime.h>
#include <cuda_fp16.h>
#include <cstdint>

#define NB  4
#define NS  2048
#define ND  512
#define NH  8
#define NDH 64

// ---------------------------------------------------------------------------
// Scratch (device globals: allocation-free rule)
// ---------------------------------------------------------------------------
__device__ __half g_qh[NB * NH * NS * NDH];   // hi only (pre-scaled)
__device__ __half g_kh[NB * NH * NS * NDH];   // hi only
__device__ __half g_vh[NB * NH * NS * NDH];   // hi only
__device__ __half g_ch[NB * NS * ND];         // ctx hi only
__device__ __half g_ah[3][NB * NS * ND];      // Q/K/V activation hi
__device__ __half g_wh[4][ND * ND];           // Wq,Wk,Wv,Wo hi

// ---------------------------------------------------------------------------
__device__ __forceinline__ uint32_t smem_u32(const void* p) {
    uint32_t a;
    asm("{ .reg .u64 t; cvta.to.shared.u64 t, %1; cvt.u32.u64 %0, t; }"
        : "=r"(a) : "l"(p));
    return a;
}
__device__ __forceinline__ void cp_async16(uint32_t dst, const void* src) {
    asm volatile("cp.async.ca.shared.global [%0], [%1], 16;"
                 :: "r"(dst), "l"(src) : "memory");
}
__device__ __forceinline__ void cp_commit() {
    asm volatile("cp.async.commit_group;" ::: "memory");
}
__device__ __forceinline__ void ldsm_x4(uint32_t addr, uint32_t& r0, uint32_t& r1,
                                        uint32_t& r2, uint32_t& r3) {
    asm volatile("ldmatrix.sync.aligned.m8n8.x4.shared.b16 {%0,%1,%2,%3}, [%4];"
                 : "=r"(r0), "=r"(r1), "=r"(r2), "=r"(r3) : "r"(addr));
}
__device__ __forceinline__ void ldsm_x4_t(uint32_t addr, uint32_t& r0, uint32_t& r1,
                                          uint32_t& r2, uint32_t& r3) {
    asm volatile("ldmatrix.sync.aligned.m8n8.x4.trans.shared.b16 {%0,%1,%2,%3}, [%4];"
                 : "=r"(r0), "=r"(r1), "=r"(r2), "=r"(r3) : "r"(addr));
}
__device__ __forceinline__ void mma16816(float* c, const uint32_t* a, const uint32_t* b) {
    asm volatile(
        "mma.sync.aligned.m16n8k16.row.col.f32.f16.f16.f32 "
        "{%0,%1,%2,%3}, {%4,%5,%6,%7}, {%8,%9}, {%0,%1,%2,%3};"
        : "+f"(c[0]), "+f"(c[1]), "+f"(c[2]), "+f"(c[3])
        : "r"(a[0]), "r"(a[1]), "r"(a[2]), "r"(a[3]), "r"(b[0]), "r"(b[1]));
}
__device__ __forceinline__ float ex2(float x) {
    float y;
    asm("ex2.approx.ftz.f32 %0, %1;" : "=f"(y) : "f"(x));
    return y;
}
__device__ __forceinline__ uint32_t pack_h2(float a, float b) {
    __half2 t = __floats2half2_rn(a, b);
    return *(uint32_t*)&t;
}

// ---------------------------------------------------------------------------
// Merged conversions (fp32 -> fp16 hi), 2 x float4 per thread
// ---------------------------------------------------------------------------
__device__ __forceinline__ void conv8(const float* in, __half* hi, int idx, int n4) {
#pragma unroll
    for (int j = 0; j < 2; ++j) {
        int i = idx + j;
        if (i < n4) {
            float4 v = ((const float4*)in)[i];
            __half h[4] = {__float2half_rn(v.x), __float2half_rn(v.y),
                           __float2half_rn(v.z), __float2half_rn(v.w)};
            ((uint2*)hi)[i] = *(uint2*)h;
        }
    }
}

__global__ __launch_bounds__(256) void conv_w4(
    const float* w0, const float* w1, const float* w2, const float* w3,
    __half* h0, __half* h1, __half* h2, __half* h3, int n4)
{
    const float* in; __half* hi;
    switch (blockIdx.y) {
        case 0:  in = w0; hi = h0; break;
        case 1:  in = w1; hi = h1; break;
        case 2:  in = w2; hi = h2; break;
        default: in = w3; hi = h3; break;
    }
    conv8(in, hi, (blockIdx.x * 256 + threadIdx.x) * 2, n4);
}

__global__ __launch_bounds__(256) void conv_a3(
    const float* a0, const float* a1, const float* a2,
    __half* h0, __half* h1, __half* h2, int n4)
{
    const float* in; __half* hi;
    switch (blockIdx.y) {
        case 0:  in = a0; hi = h0; break;
        case 1:  in = a1; hi = h1; break;
        default: in = a2; hi = h2; break;
    }
    conv8(in, hi, (blockIdx.x * 256 + threadIdx.x) * 2, n4);
}

// ---------------------------------------------------------------------------
// HMMA projection GEMM body: C[8192,512] = X @ W^T + bias
// Single product (A hi x B hi), BK=64 chunks, double-buffered, 2 CTAs/SM.
// MODE 0: fp32 row-major out. MODE 1: fp16 hi out, head layout, scaled.
// ---------------------------------------------------------------------------
#define ROWB   144           // 64 halves (128B) + 16B pad
#define ARRSZ  (128 * ROWB)  // 18432
#define STG    (2 * ARRSZ)
#define PROJ_SMEM (2 * STG)  // 73728

template <int MODE>
__device__ __forceinline__ void proj_body(
    const __half* __restrict__ Ah, const __half* __restrict__ Bh,
    const float* __restrict__ bias, float* __restrict__ outF,
    __half* __restrict__ outH, float scale, char* smem)
{
    const uint32_t sb = smem_u32(smem);
    const int tid  = threadIdx.x;
    const int lane = tid & 31;
    const int wid  = tid >> 5;
    const int warp_m = wid & 3;
    const int warp_n = wid >> 2;
    const int m0 = blockIdx.x * 128;
    const int n0 = blockIdx.y * 128;

    const uint32_t a_off = (uint32_t)((warp_m * 32 + (lane & 15)) * ROWB + (lane >> 4) * 16);
    const uint32_t b_off = (uint32_t)((warp_n * 64 + (lane & 7) + 8 * (lane >> 4)) * ROWB
                                      + ((lane >> 3) & 1) * 16);

    float acc[2][8][4];
#pragma unroll
    for (int mi = 0; mi < 2; ++mi)
#pragma unroll
        for (int ni = 0; ni < 8; ++ni)
#pragma unroll
            for (int q = 0; q < 4; ++q) acc[mi][ni][q] = 0.0f;

    auto load_chunk = [&](int c, int stage) {
        const int k0 = c * 64;
        const uint32_t st = sb + stage * STG;
#pragma unroll
        for (int i = 0; i < 4; ++i) {
            const int c2 = tid + i * 256;
            const int r  = c2 >> 3;
            const int g  = c2 & 7;
            cp_async16(st + r * ROWB + g * 16,
                       Ah + (m0 + r) * ND + k0 + g * 8);
            cp_async16(st + ARRSZ + r * ROWB + g * 16,
                       Bh + (n0 + r) * ND + k0 + g * 8);
        }
        cp_commit();
    };

    load_chunk(0, 0);

    for (int c = 0; c < 8; ++c) {
        const int stage = c & 1;
        if (c < 7) {
            load_chunk(c + 1, stage ^ 1);
            asm volatile("cp.async.wait_group 1;" ::: "memory");
        } else {
            asm volatile("cp.async.wait_group 0;" ::: "memory");
        }
        __syncthreads();

        const uint32_t st = sb + stage * STG;
#pragma unroll
        for (int ks = 0; ks < 4; ++ks) {
            const uint32_t kb = ks * 32;
            uint32_t ah[2][4];
#pragma unroll
            for (int mi = 0; mi < 2; ++mi) {
                uint32_t adr = st + a_off + mi * (16 * ROWB) + kb;
                ldsm_x4(adr, ah[mi][0], ah[mi][1], ah[mi][2], ah[mi][3]);
            }
#pragma unroll
            for (int nb = 0; nb < 4; ++nb) {
                uint32_t adr = st + ARRSZ + b_off + nb * (16 * ROWB) + kb;
                uint32_t t0, t1, t2, t3;
                ldsm_x4(adr, t0, t1, t2, t3);
                uint32_t bhA[2] = {t0, t1}, bhB[2] = {t2, t3};
#pragma unroll
                for (int mi = 0; mi < 2; ++mi) {
                    mma16816(acc[mi][nb*2],   ah[mi], bhA);
                    mma16816(acc[mi][nb*2+1], ah[mi], bhB);
                }
            }
        }
        __syncthreads();
    }

    const int crow = lane >> 2;
    const int ccol = (lane & 3) * 2;
#pragma unroll
    for (int mi = 0; mi < 2; ++mi) {
#pragma unroll
        for (int half = 0; half < 2; ++half) {
            const int m = m0 + warp_m * 32 + mi * 16 + crow + half * 8;
            const int b = m >> 11, s = m & 2047;
#pragma unroll
            for (int ni = 0; ni < 8; ++ni) {
                const int n = n0 + warp_n * 64 + ni * 8 + ccol;
                float v0 = acc[mi][ni][half * 2 + 0] + bias[n];
                float v1 = acc[mi][ni][half * 2 + 1] + bias[n + 1];
                if (MODE == 1) {
                    v0 *= scale; v1 *= scale;
                    const int head = n >> 6, d = n & 63;
                    const int idx = ((b * NH + head) * NS + s) * NDH + d;
                    *(uint32_t*)&outH[idx] = pack_h2(v0, v1);
                } else {
                    *(float2*)&outF[m * ND + n] = make_float2(v0, v1);
                }
            }
        }
    }
}

// Fused Q/K/V projections, persistent z-loop: grid (64,4), one wave.
__global__ __launch_bounds__(256, 2) void proj_qkv(
    const __half* AhQ, const __half* BhQ, const float* biasQ, __half* outQ, float scaleQ,
    const __half* AhK, const __half* BhK, const float* biasK, __half* outK,
    const __half* AhV, const __half* BhV, const float* biasV, __half* outV)
{
    extern __shared__ char smem[];
#pragma unroll 1
    for (int z = 0; z < 3; ++z) {
        const __half *Ah, *Bh; const float* bias; __half* outH; float scale;
        if (z == 0)      { Ah = AhQ; Bh = BhQ; bias = biasQ; outH = outQ; scale = scaleQ; }
        else if (z == 1) { Ah = AhK; Bh = BhK; bias = biasK; outH = outK; scale = 1.0f; }
        else             { Ah = AhV; Bh = BhV; bias = biasV; outH = outV; scale = 1.0f; }
        proj_body<1>(Ah, Bh, bias, nullptr, outH, scale, smem);
        __syncthreads();
    }
}

// Output projection, fp32 out
__global__ __launch_bounds__(256, 2) void proj_o(
    const __half* Ah, const __half* Bh, const float* bias, float* outF)
{
    extern __shared__ char smem[];
    proj_body<0>(Ah, Bh, bias, outF, nullptr, 1.0f, smem);
}

// ---------------------------------------------------------------------------
// HMMA flash attention. CTA = 128 q rows x one (b,h), 8 warps, KV tile 64,
// 3-stage cp.async pipeline, 2 CTAs/SM. q/k/v/P/ctx all fp16 hi.
// q pre-scaled by 0.125*log2(e); softmax in log2 domain.
// Masking applied only on the final KV tile.
// ---------------------------------------------------------------------------
#define QROWB 144
#define QARR  18432
#define KARRA 9216
#define KVSTG (2 * KARRA)                 // 18432 per stage
#define ATTN_SMEM (QARR + 3 * KVSTG)      // 73728

__global__ __launch_bounds__(256, 2) void attn_hmma(
    const __half* __restrict__ qh,
    const __half* __restrict__ kh, const __half* __restrict__ vh,
    __half* __restrict__ ch,
    const void* __restrict__ masked_raw)
{
    extern __shared__ char smem[];
    const uint32_t sb = smem_u32(smem);
    const int tid  = threadIdx.x;
    const int lane = tid & 31;
    const int wid  = tid >> 5;
    const int bh   = blockIdx.y;
    const int b    = bh >> 3;
    const int h    = bh & 7;
    const int q0   = blockIdx.x << 7;
    const int gbase = bh * NS * NDH;

    int len;
    {
        const long long* ml = (const long long*)masked_raw;
        long long probe = ml[0];
        if (probe >= 1 && probe <= NS) len = (int)ml[b];
        else                           len = ((const int*)masked_raw)[b];
    }
    const int ntiles = (len + 63) >> 6;

    // Load Q hi into smem
#pragma unroll
    for (int i = 0; i < 4; ++i) {
        int c = tid + i * 256;
        int r = c >> 3, blk = c & 7;
        *(uint4*)(smem + r * QROWB + blk * 16) =
            *(const uint4*)(qh + gbase + (q0 + r) * NDH + blk * 8);
    }

    auto load_kv = [&](int t) {
        const uint32_t s0 = sb + QARR + (t % 3) * KVSTG;
        const int gk = gbase + (t << 6) * NDH;
#pragma unroll
        for (int i = 0; i < 2; ++i) {
            int c = tid + i * 256;
            int r = c >> 3, blk = c & 7;
            const uint32_t dst = s0 + r * QROWB + blk * 16;
            const int src = gk + r * NDH + blk * 8;
            cp_async16(dst,         kh + src);
            cp_async16(dst + KARRA, vh + src);
        }
        cp_commit();
    };

    load_kv(0);
    if (ntiles > 1) load_kv(1);
    __syncthreads();   // Q smem ready

    uint32_t qf[4][4];
    {
        const uint32_t qa = sb + (wid * 16 + (lane & 15)) * QROWB + (lane >> 4) * 16;
#pragma unroll
        for (int ks = 0; ks < 4; ++ks)
            ldsm_x4(qa + ks * 32, qf[ks][0], qf[ks][1], qf[ks][2], qf[ks][3]);
    }

    float m0r = -1e30f, m1r = -1e30f, lsum0 = 0.0f, lsum1 = 0.0f;
    float o[8][4];
#pragma unroll
    for (int di = 0; di < 8; ++di)
#pragma unroll
        for (int q = 0; q < 4; ++q) o[di][q] = 0.0f;

    for (int t = 0; t < ntiles; ++t) {
        if (t + 2 < ntiles) load_kv(t + 2);
        {
            int pend = ntiles - 1 - t;
            if (pend > 2) pend = 2;
            if (pend == 2)      asm volatile("cp.async.wait_group 2;" ::: "memory");
            else if (pend == 1) asm volatile("cp.async.wait_group 1;" ::: "memory");
            else                asm volatile("cp.async.wait_group 0;" ::: "memory");
        }
        __syncthreads();

        const uint32_t kbase = sb + QARR + (t % 3) * KVSTG;

        // ---- S = Q K^T (per-warp 16 x 64) ----
        float s[8][4];
#pragma unroll
        for (int ni = 0; ni < 8; ++ni)
#pragma unroll
            for (int q = 0; q < 4; ++q) s[ni][q] = 0.0f;

#pragma unroll
        for (int ks = 0; ks < 4; ++ks) {
#pragma unroll
            for (int nb = 0; nb < 4; ++nb) {
                const uint32_t adr = kbase
                    + (nb * 16 + (lane & 7) + 8 * (lane >> 4)) * QROWB
                    + ((lane >> 3) & 1) * 16 + ks * 32;
                uint32_t t0, t1, t2, t3;
                ldsm_x4(adr, t0, t1, t2, t3);
                uint32_t bh0[2] = {t0, t1}, bh1[2] = {t2, t3};
                mma16816(s[nb*2],   qf[ks], bh0);
                mma16816(s[nb*2+1], qf[ks], bh1);
            }
        }

        // ---- mask (last tile only) + online softmax (log2 domain) ----
        if (t == ntiles - 1) {
            const int cb = (t << 6) + 2 * (lane & 3);
#pragma unroll
            for (int ni = 0; ni < 8; ++ni) {
                const int c0 = cb + 8 * ni;
                if (c0     >= len) { s[ni][0] = -1e30f; s[ni][2] = -1e30f; }
                if (c0 + 1 >= len) { s[ni][1] = -1e30f; s[ni][3] = -1e30f; }
            }
        }
        float tmax0 = -1e30f, tmax1 = -1e30f;
#pragma unroll
        for (int ni = 0; ni < 8; ++ni) {
            tmax0 = fmaxf(tmax0, fmaxf(s[ni][0], s[ni][1]));
            tmax1 = fmaxf(tmax1, fmaxf(s[ni][2], s[ni][3]));
        }
        tmax0 = fmaxf(tmax0, __shfl_xor_sync(0xffffffffu, tmax0, 1));
        tmax0 = fmaxf(tmax0, __shfl_xor_sync(0xffffffffu, tmax0, 2));
        tmax1 = fmaxf(tmax1, __shfl_xor_sync(0xffffffffu, tmax1, 1));
        tmax1 = fmaxf(tmax1, __shfl_xor_sync(0xffffffffu, tmax1, 2));

        const float mn0 = fmaxf(m0r, tmax0);
        const float mn1 = fmaxf(m1r, tmax1);
        const float sc0 = ex2(m0r - mn0);
        const float sc1 = ex2(m1r - mn1);
        m0r = mn0; m1r = mn1;

        float ps0 = 0.0f, ps1 = 0.0f;
#pragma unroll
        for (int ni = 0; ni < 8; ++ni) {
            float p0 = ex2(s[ni][0] - mn0);
            float p1 = ex2(s[ni][1] - mn0);
            float p2 = ex2(s[ni][2] - mn1);
            float p3 = ex2(s[ni][3] - mn1);
            ps0 += p0 + p1;
            ps1 += p2 + p3;
            s[ni][0] = __uint_as_float(pack_h2(p0, p1));
            s[ni][2] = __uint_as_float(pack_h2(p2, p3));
        }
        ps0 += __shfl_xor_sync(0xffffffffu, ps0, 1);
        ps0 += __shfl_xor_sync(0xffffffffu, ps0, 2);
        ps1 += __shfl_xor_sync(0xffffffffu, ps1, 1);
        ps1 += __shfl_xor_sync(0xffffffffu, ps1, 2);
        lsum0 = lsum0 * sc0 + ps0;
        lsum1 = lsum1 * sc1 + ps1;
#pragma unroll
        for (int di = 0; di < 8; ++di) {
            o[di][0] *= sc0; o[di][1] *= sc0;
            o[di][2] *= sc1; o[di][3] *= sc1;
        }

        // ---- O += P V ----
        const uint32_t vbase = kbase + KARRA;
#pragma unroll
        for (int ks2 = 0; ks2 < 4; ++ks2) {
            uint32_t Ahf[4] = {
                __float_as_uint(s[2*ks2][0]),   __float_as_uint(s[2*ks2][2]),
                __float_as_uint(s[2*ks2+1][0]), __float_as_uint(s[2*ks2+1][2]) };
#pragma unroll
            for (int db = 0; db < 4; ++db) {
                const uint32_t adr = vbase
                    + (ks2 * 16 + (lane & 7) + 8 * ((lane >> 3) & 1)) * QROWB
                    + ((lane >> 4) & 1) * 16 + db * 32;
                uint32_t t0, t1, t2, t3;
                ldsm_x4_t(adr, t0, t1, t2, t3);
                uint32_t vh0[2] = {t0, t1}, vh1[2] = {t2, t3};
                mma16816(o[db*2],   Ahf, vh0);
                mma16816(o[db*2+1], Ahf, vh1);
            }
        }
        __syncthreads();
    }

    // ---- normalize + write ctx hi [B,S,D] ----
    const float inv0 = 1.0f / lsum0;
    const float inv1 = 1.0f / lsum1;
    const int r  = lane >> 2;
    const int dc = 2 * (lane & 3);
    const int qrow0 = q0 + wid * 16 + r;
#pragma unroll
    for (int di = 0; di < 8; ++di) {
        const int d = 8 * di + dc;
        *(uint32_t*)&ch[((b * NS + qrow0) * ND) + h * NDH + d] =
            pack_h2(o[di][0] * inv0, o[di][1] * inv0);
        *(uint32_t*)&ch[((b * NS + qrow0 + 8) * ND) + h * NDH + d] =
            pack_h2(o[di][2] * inv1, o[di][3] * inv1);
    }
}

// ---------------------------------------------------------------------------
extern "C" void kernel_launch(void* const* d_in, const int* in_sizes, int n_in,
                              void* d_out, int out_size)
{
    (void)in_sizes; (void)n_in; (void)out_size;
    const float* Q  = (const float*)d_in[0];
    const float* K  = (const float*)d_in[1];
    const float* V  = (const float*)d_in[2];
    const float* Wq = (const float*)d_in[3];
    const float* bq = (const float*)d_in[4];
    const float* Wk = (const float*)d_in[5];
    const float* bk = (const float*)d_in[6];
    const float* Wv = (const float*)d_in[7];
    const float* bv = (const float*)d_in[8];
    const float* Wo = (const float*)d_in[9];
    const float* bo = (const float*)d_in[10];
    const void*  mk = d_in[11];
    float* out = (float*)d_out;

    __half *pqh, *pkh, *pvh, *pch, *pah, *pwh;
    cudaGetSymbolAddress((void**)&pqh, g_qh);
    cudaGetSymbolAddress((void**)&pkh, g_kh);
    cudaGetSymbolAddress((void**)&pvh, g_vh);
    cudaGetSymbolAddress((void**)&pch, g_ch);
    cudaGetSymbolAddress((void**)&pah, g_ah);
    cudaGetSymbolAddress((void**)&pwh, g_wh);

    const int NACT = NB * NS * ND;   // 4194304
    const int NW   = ND * ND;        // 262144
    const int nx4 = NACT / 4;
    const int nw4 = NW / 4;

    cudaFuncSetAttribute((const void*)proj_qkv,
                         cudaFuncAttributeMaxDynamicSharedMemorySize, PROJ_SMEM);
    cudaFuncSetAttribute((const void*)proj_o,
                         cudaFuncAttributeMaxDynamicSharedMemorySize, PROJ_SMEM);
    cudaFuncSetAttribute((const void*)attn_hmma,
                         cudaFuncAttributeMaxDynamicSharedMemorySize, ATTN_SMEM);

    const float QSCALE = 0.125f * 1.4426950408889634f;  // 1/sqrt(64) * log2(e)

    // 1) weight hi conversions (4 in one launch, 32B/thread)
    conv_w4<<<dim3((nw4 / 2 + 255) / 256, 4), 256>>>(
        Wq, Wk, Wv, Wo, pwh, pwh + NW, pwh + 2 * NW, pwh + 3 * NW, nw4);
    // 2) activation hi conversions (3 in one launch, 32B/thread)
    conv_a3<<<dim3((nx4 / 2 + 255) / 256, 3), 256>>>(
        Q, K, V, pah, pah + NACT, pah + 2 * NACT, nx4);
    // 3) fused Q/K/V projections (persistent z-loop, single wave)
    proj_qkv<<<dim3(64, 4), 256, PROJ_SMEM>>>(
        pah,            pwh,          bq, pqh, QSCALE,
        pah + NACT,     pwh + NW,     bk, pkh,
        pah + 2 * NACT, pwh + 2 * NW, bv, pvh);
    // 4) attention
    attn_hmma<<<dim3(NS / 128, NB * NH), 256, ATTN_SMEM>>>(
        pqh, pkh, pvh, pch, mk);
    // 5) output projection
    proj_o<<<dim3(64, 4), 256, PROJ_SMEM>>>(
        pch, pwh + 3 * NW, bo, out);
}